// round 1
// baseline (speedup 1.0000x reference)
#include <cuda_runtime.h>

#define NB 8
#define NSP 16384
#define NCLS 21
#define CDIM 256
#define KCDIM 128
#define EPS_GN 1e-5f

// ----------------------------- scratch (device globals, no allocation) -----
__device__ float  g_probs[(size_t)NB*NCLS*NSP];          // 11 MB
__device__ float  g_ctx  [NB*CDIM*NCLS];
__device__ float  g_kmat [NB*KCDIM*NCLS];
__device__ float  g_vmat [NB*KCDIM*NCLS];
__device__ float  g_q1   [(size_t)NB*KCDIM*NSP];          // 64 MB
__device__ float  g_q2   [(size_t)NB*KCDIM*NSP];          // 64 MB
__device__ float  g_att  [(size_t)NB*KCDIM*NSP];          // 64 MB
__device__ float  g_up   [(size_t)NB*CDIM*NSP];           // 128 MB
__device__ float2 g_part [NB*256];
__device__ float2 g_stats[4*NB];                          // stage: 0=q1 1=q2 2=up 3=out

// ----------------------------- probs: bilinear(align_corners) + softmax ----
__global__ __launch_bounds__(256) void k_probs(const float* __restrict__ aux)
{
    int b = blockIdx.x / NCLS, k = blockIdx.x % NCLS;
    const float* src = aux + ((size_t)b*NCLS + k)*64*64;
    float* dst = g_probs + ((size_t)b*NCLS + k)*NSP;
    int tid = threadIdx.x;
    __shared__ float red[256];
    __shared__ float bc;
    const float sc = 63.f/127.f;

    float mx = -3.4e38f;
    for (int n = tid; n < NSP; n += 256) {
        int y = n >> 7, x = n & 127;
        float sy = y*sc, sx = x*sc;
        int y0 = (int)sy, x0 = (int)sx;
        float fy = sy - (float)y0, fx = sx - (float)x0;
        int y1 = min(y0+1, 63), x1 = min(x0+1, 63);
        float a00 = src[y0*64+x0], a01 = src[y0*64+x1];
        float a10 = src[y1*64+x0], a11 = src[y1*64+x1];
        float top = a00 + (a01-a00)*fx;
        float bot = a10 + (a11-a10)*fx;
        float v = top + (bot-top)*fy;
        dst[n] = v;
        mx = fmaxf(mx, v);
    }
    red[tid] = mx; __syncthreads();
    for (int s = 128; s > 0; s >>= 1) { if (tid < s) red[tid] = fmaxf(red[tid], red[tid+s]); __syncthreads(); }
    if (tid == 0) bc = red[0];
    __syncthreads();
    mx = bc;

    float sum = 0.f;
    for (int n = tid; n < NSP; n += 256) {
        float e = __expf(dst[n] - mx);
        dst[n] = e;
        sum += e;
    }
    __syncthreads();
    red[tid] = sum; __syncthreads();
    for (int s = 128; s > 0; s >>= 1) { if (tid < s) red[tid] += red[tid+s]; __syncthreads(); }
    if (tid == 0) bc = 1.f / red[0];
    __syncthreads();
    float inv = bc;
    for (int n = tid; n < NSP; n += 256) dst[n] *= inv;
}

// ----------------------------- ctx = probs @ feats^T : [b,256,21] ----------
__global__ __launch_bounds__(256) void k_ctx(const float* __restrict__ feats)
{
    __shared__ float p_s[NCLS*128];
    __shared__ float f_s[64*129];
    int b = blockIdx.y, c0 = blockIdx.x * 64;
    int tid = threadIdx.x;
    int tx = tid & 63, ty = tid >> 6;       // tx: channel within chunk, ty: m group
    float acc[6] = {0,0,0,0,0,0};

    for (int k0 = 0; k0 < NSP; k0 += 128) {
        for (int e = tid; e < NCLS*128; e += 256) {
            int m = e >> 7, kk = e & 127;
            p_s[e] = g_probs[((size_t)b*NCLS + m)*NSP + k0 + kk];
        }
        for (int e = tid; e < 64*128; e += 256) {
            int r = e >> 7, kk = e & 127;
            f_s[r*129 + kk] = feats[((size_t)b*CDIM + c0 + r)*NSP + k0 + kk];
        }
        __syncthreads();
        for (int kk = 0; kk < 128; kk++) {
            float fv = f_s[tx*129 + kk];
            #pragma unroll
            for (int i = 0; i < 6; i++) {
                int m = ty + 4*i;
                if (m < NCLS) acc[i] += p_s[m*128 + kk] * fv;
            }
        }
        __syncthreads();
    }
    #pragma unroll
    for (int i = 0; i < 6; i++) {
        int m = ty + 4*i;
        if (m < NCLS) g_ctx[((size_t)b*CDIM + c0 + tx)*NCLS + m] = acc[i];
    }
}

// ----------------------------- tiny object branch: k,v [b,128,21] ----------
__global__ __launch_bounds__(256) void k_small(
    const float* __restrict__ fo_w1, const float* __restrict__ fo_g1, const float* __restrict__ fo_b1,
    const float* __restrict__ fo_w2, const float* __restrict__ fo_g2, const float* __restrict__ fo_b2,
    const float* __restrict__ fd_w,  const float* __restrict__ fd_g,  const float* __restrict__ fd_b)
{
    __shared__ float ctx_s[CDIM*NCLS];     // 5376
    __shared__ float t_s[KCDIM*NCLS];      // 2688
    __shared__ float u_s[KCDIM*NCLS];      // 2688
    __shared__ float red[256];
    __shared__ float red2[256];
    __shared__ float2 mv;
    int b = blockIdx.x, tid = threadIdx.x;

    for (int e = tid; e < CDIM*NCLS; e += 256) ctx_s[e] = g_ctx[(size_t)b*CDIM*NCLS + e];
    __syncthreads();

    // helper macro-style GN over a 2688 buffer with per-o affine + relu
    #define SMALL_GN(buf, gam, bet)                                                         \
    {                                                                                       \
        float s = 0.f, q = 0.f;                                                             \
        for (int e = tid; e < KCDIM*NCLS; e += 256) { float v = buf[e]; s += v; q += v*v; } \
        red[tid] = s; red2[tid] = q; __syncthreads();                                       \
        for (int st = 128; st > 0; st >>= 1) {                                              \
            if (tid < st) { red[tid] += red[tid+st]; red2[tid] += red2[tid+st]; }           \
            __syncthreads();                                                                \
        }                                                                                   \
        if (tid == 0) {                                                                     \
            float m = red[0] / (KCDIM*NCLS);                                                \
            float var = red2[0] / (KCDIM*NCLS) - m*m;                                       \
            mv.x = m; mv.y = rsqrtf(var + EPS_GN);                                          \
        }                                                                                   \
        __syncthreads();                                                                    \
        float m = mv.x, r = mv.y;                                                           \
        for (int e = tid; e < KCDIM*NCLS; e += 256) {                                       \
            int o = e / NCLS;                                                               \
            float v = (buf[e] - m) * r * gam[o] + bet[o];                                   \
            buf[e] = fmaxf(v, 0.f);                                                         \
        }                                                                                   \
        __syncthreads();                                                                    \
    }

    // conv1: t = fo_w1 @ ctx  (K=256)
    for (int e = tid; e < KCDIM*NCLS; e += 256) {
        int o = e / NCLS, kk = e % NCLS;
        float s = 0.f;
        for (int c = 0; c < CDIM; c++) s += fo_w1[o*CDIM + c] * ctx_s[c*NCLS + kk];
        t_s[e] = s;
    }
    __syncthreads();
    SMALL_GN(t_s, fo_g1, fo_b1)
    // conv2: u = fo_w2 @ t  (K=128)
    for (int e = tid; e < KCDIM*NCLS; e += 256) {
        int o = e / NCLS, kk = e % NCLS;
        float s = 0.f;
        for (int c = 0; c < KCDIM; c++) s += fo_w2[o*KCDIM + c] * t_s[c*NCLS + kk];
        u_s[e] = s;
    }
    __syncthreads();
    SMALL_GN(u_s, fo_g2, fo_b2)
    for (int e = tid; e < KCDIM*NCLS; e += 256) g_kmat[(size_t)b*KCDIM*NCLS + e] = u_s[e];
    __syncthreads();
    // v = gn(relu(fd_w @ ctx))
    for (int e = tid; e < KCDIM*NCLS; e += 256) {
        int o = e / NCLS, kk = e % NCLS;
        float s = 0.f;
        for (int c = 0; c < CDIM; c++) s += fd_w[o*CDIM + c] * ctx_s[c*NCLS + kk];
        t_s[e] = s;
    }
    __syncthreads();
    SMALL_GN(t_s, fd_g, fd_b)
    for (int e = tid; e < KCDIM*NCLS; e += 256) g_vmat[(size_t)b*KCDIM*NCLS + e] = t_s[e];
    #undef SMALL_GN
}

// ----------------------------- main conv GEMM (128x128 tile, 8x8/thread) ---
// Y[b,o,n] = sum_k W[o,k] * X[b,k,n], with optional GN+relu transform on Xa
// (for k < Ka) and optional raw second source Xb (for k >= Ka, concat case).
__global__ __launch_bounds__(256) void k_conv(
    const float* __restrict__ W, const float* __restrict__ Xa,
    int stats_stage, const float* __restrict__ ga, const float* __restrict__ ba,
    int Ka, const float* __restrict__ Xb,
    float* __restrict__ Y, int K, int O)
{
    __shared__ float A_s[8][132];
    __shared__ float B_s[8][128];
    int b = blockIdx.z;
    int n0 = blockIdx.x * 128, o0 = blockIdx.y * 128;
    int tid = threadIdx.x;
    int tx = tid & 15, ty = tid >> 4;

    float mean = 0.f, rstd = 0.f;
    if (stats_stage >= 0) { float2 st = g_stats[stats_stage*NB + b]; mean = st.x; rstd = st.y; }

    float acc[8][8];
    #pragma unroll
    for (int i = 0; i < 8; i++)
        #pragma unroll
        for (int j = 0; j < 8; j++) acc[i][j] = 0.f;

    for (int k0 = 0; k0 < K; k0 += 8) {
        #pragma unroll
        for (int l = 0; l < 4; l++) {
            int e = tid + l*256;
            int o = e >> 3, kk = e & 7;
            A_s[kk][o] = W[(size_t)(o0+o)*K + k0 + kk];
        }
        #pragma unroll
        for (int l = 0; l < 4; l++) {
            int e = tid + l*256;
            int c = e & 127, kk = e >> 7;
            int k = k0 + kk;
            float v;
            if (k < Ka) {
                v = Xa[((size_t)b*Ka + k)*NSP + n0 + c];
                if (stats_stage >= 0) {
                    v = (v - mean)*rstd*ga[k] + ba[k];
                    v = fmaxf(v, 0.f);
                }
            } else {
                v = Xb[((size_t)b*(K-Ka) + (k-Ka))*NSP + n0 + c];
            }
            B_s[kk][c] = v;
        }
        __syncthreads();
        #pragma unroll
        for (int kk = 0; kk < 8; kk++) {
            float4 a0 = *(const float4*)&A_s[kk][ty*4];
            float4 a1 = *(const float4*)&A_s[kk][64 + ty*4];
            float4 b0 = *(const float4*)&B_s[kk][tx*4];
            float4 b1 = *(const float4*)&B_s[kk][64 + tx*4];
            float av[8] = {a0.x,a0.y,a0.z,a0.w,a1.x,a1.y,a1.z,a1.w};
            float bv[8] = {b0.x,b0.y,b0.z,b0.w,b1.x,b1.y,b1.z,b1.w};
            #pragma unroll
            for (int i = 0; i < 8; i++)
                #pragma unroll
                for (int j = 0; j < 8; j++) acc[i][j] += av[i]*bv[j];
        }
        __syncthreads();
    }

    #pragma unroll
    for (int i = 0; i < 8; i++) {
        int o = o0 + ((i < 4) ? (ty*4 + i) : (64 + ty*4 + i - 4));
        float* yr = Y + ((size_t)b*O + o)*NSP + n0;
        float4 v0 = make_float4(acc[i][0], acc[i][1], acc[i][2], acc[i][3]);
        float4 v1 = make_float4(acc[i][4], acc[i][5], acc[i][6], acc[i][7]);
        *(float4*)&yr[tx*4]      = v0;
        *(float4*)&yr[64+tx*4]   = v1;
    }
}

// ----------------------------- GN stats: partial + final -------------------
__global__ __launch_bounds__(256) void k_stats_part(const float* __restrict__ src, int CN)
{
    int b = blockIdx.y, p = blockIdx.x;
    int chunk = CN >> 8;
    const float* s = src + (size_t)b*CN + (size_t)p*chunk;
    __shared__ float red[256];
    __shared__ float red2[256];
    float sm = 0.f, sq = 0.f;
    for (int i = threadIdx.x; i < chunk; i += 256) { float v = s[i]; sm += v; sq += v*v; }
    int tid = threadIdx.x;
    red[tid] = sm; red2[tid] = sq; __syncthreads();
    for (int st = 128; st > 0; st >>= 1) {
        if (tid < st) { red[tid] += red[tid+st]; red2[tid] += red2[tid+st]; }
        __syncthreads();
    }
    if (tid == 0) g_part[b*256 + p] = make_float2(red[0], red2[0]);
}

__global__ __launch_bounds__(256) void k_stats_fin(int CN, int stage)
{
    int b = blockIdx.x, tid = threadIdx.x;
    __shared__ float red[256];
    __shared__ float red2[256];
    float2 v = g_part[b*256 + tid];
    red[tid] = v.x; red2[tid] = v.y; __syncthreads();
    for (int st = 128; st > 0; st >>= 1) {
        if (tid < st) { red[tid] += red[tid+st]; red2[tid] += red2[tid+st]; }
        __syncthreads();
    }
    if (tid == 0) {
        float m = red[0] / (float)CN;
        float var = red2[0] / (float)CN - m*m;
        g_stats[stage*NB + b] = make_float2(m, rsqrtf(var + EPS_GN));
    }
}

// ----------------------------- attention: sim softmax + att ----------------
// q = GN(stage1, fp_g2, fp_b2) + relu applied to g_q2 on load.
__global__ __launch_bounds__(128) void k_attn(const float* __restrict__ g2, const float* __restrict__ b2)
{
    extern __shared__ float sm[];
    float* q_s = sm;                 // 128 c x 128 px
    float* k_s = sm + KCDIM*128;     // 128 x 21
    float* v_s = k_s + KCDIM*NCLS;   // 128 x 21
    int b = blockIdx.y, n0 = blockIdx.x * 128;
    int tid = threadIdx.x;

    float2 st = g_stats[1*NB + b];
    float mean = st.x, rstd = st.y;

    for (int e = tid; e < KCDIM*128; e += 128) {
        int c = e >> 7, px = e & 127;
        float raw = g_q2[((size_t)b*KCDIM + c)*NSP + n0 + px];
        float v = (raw - mean)*rstd*g2[c] + b2[c];
        q_s[c*128 + px] = fmaxf(v, 0.f);
    }
    for (int e = tid; e < KCDIM*NCLS; e += 128) {
        k_s[e] = g_kmat[(size_t)b*KCDIM*NCLS + e];
        v_s[e] = g_vmat[(size_t)b*KCDIM*NCLS + e];
    }
    __syncthreads();

    int px = tid;
    float s[NCLS];
    #pragma unroll
    for (int kk = 0; kk < NCLS; kk++) s[kk] = 0.f;
    for (int c = 0; c < KCDIM; c++) {
        float qv = q_s[c*128 + px];
        #pragma unroll
        for (int kk = 0; kk < NCLS; kk++) s[kk] += qv * k_s[c*NCLS + kk];
    }
    const float scale = 0.0883883476483184f;  // 128^-0.5
    float mx = -3.4e38f;
    #pragma unroll
    for (int kk = 0; kk < NCLS; kk++) { s[kk] *= scale; mx = fmaxf(mx, s[kk]); }
    float ssum = 0.f;
    #pragma unroll
    for (int kk = 0; kk < NCLS; kk++) { s[kk] = __expf(s[kk] - mx); ssum += s[kk]; }
    float inv = 1.f / ssum;
    #pragma unroll
    for (int kk = 0; kk < NCLS; kk++) s[kk] *= inv;

    for (int c = 0; c < KCDIM; c++) {
        float a = 0.f;
        #pragma unroll
        for (int kk = 0; kk < NCLS; kk++) a += s[kk] * v_s[c*NCLS + kk];
        g_att[((size_t)b*KCDIM + c)*NSP + n0 + px] = a;
    }
}

// ----------------------------- final GN + relu on d_out --------------------
__global__ __launch_bounds__(256) void k_gnfinal(float* __restrict__ Y,
                                                 const float* __restrict__ g,
                                                 const float* __restrict__ bb)
{
    size_t e = ((size_t)blockIdx.x*256 + threadIdx.x)*4;
    int b = (int)(e / ((size_t)CDIM*NSP));
    int c = (int)((e / NSP) & (CDIM-1));
    float2 st = g_stats[3*NB + b];
    float m = st.x, r = st.y;
    float gm = g[c], bt = bb[c];
    float4 v = *(float4*)&Y[e];
    v.x = fmaxf((v.x - m)*r*gm + bt, 0.f);
    v.y = fmaxf((v.y - m)*r*gm + bt, 0.f);
    v.z = fmaxf((v.z - m)*r*gm + bt, 0.f);
    v.w = fmaxf((v.w - m)*r*gm + bt, 0.f);
    *(float4*)&Y[e] = v;
}

// ----------------------------- host ----------------------------------------
extern "C" void kernel_launch(void* const* d_in, const int* in_sizes, int n_in,
                              void* d_out, int out_size)
{
    const float* feats   = (const float*)d_in[0];
    const float* out_aux = (const float*)d_in[1];
    const float* fp_w1 = (const float*)d_in[2];
    const float* fp_g1 = (const float*)d_in[3];
    const float* fp_b1 = (const float*)d_in[4];
    const float* fp_w2 = (const float*)d_in[5];
    const float* fp_g2 = (const float*)d_in[6];
    const float* fp_b2 = (const float*)d_in[7];
    const float* fo_w1 = (const float*)d_in[8];
    const float* fo_g1 = (const float*)d_in[9];
    const float* fo_b1 = (const float*)d_in[10];
    const float* fo_w2 = (const float*)d_in[11];
    const float* fo_g2 = (const float*)d_in[12];
    const float* fo_b2 = (const float*)d_in[13];
    const float* fd_w  = (const float*)d_in[14];
    const float* fd_g  = (const float*)d_in[15];
    const float* fd_b  = (const float*)d_in[16];
    const float* fu_w  = (const float*)d_in[17];
    const float* fu_g  = (const float*)d_in[18];
    const float* fu_b  = (const float*)d_in[19];
    const float* cb_w  = (const float*)d_in[20];
    const float* cb_g  = (const float*)d_in[21];
    const float* cb_b  = (const float*)d_in[22];
    float* out = (float*)d_out;

    void* p;
    cudaGetSymbolAddress(&p, g_q1);  float* q1  = (float*)p;
    cudaGetSymbolAddress(&p, g_q2);  float* q2  = (float*)p;
    cudaGetSymbolAddress(&p, g_att); float* att = (float*)p;
    cudaGetSymbolAddress(&p, g_up);  float* up  = (float*)p;

    const int attn_smem = (KCDIM*128 + 2*KCDIM*NCLS)*4;  // 87040 B
    cudaFuncSetAttribute(k_attn, cudaFuncAttributeMaxDynamicSharedMemorySize, attn_smem);

    // 1. probs (interp + softmax)
    k_probs<<<NB*NCLS, 256>>>(out_aux);
    // 2. ctx gather
    k_ctx<<<dim3(4, NB), 256>>>(feats);
    // 3. tiny object branch -> k,v
    k_small<<<NB, 256>>>(fo_w1, fo_g1, fo_b1, fo_w2, fo_g2, fo_b2, fd_w, fd_g, fd_b);
    // 4. f_pixel conv1 (raw) + stats
    k_conv<<<dim3(128, 1, NB), 256>>>(fp_w1, feats, -1, nullptr, nullptr, 256, nullptr, q1, 256, 128);
    k_stats_part<<<dim3(256, NB), 256>>>(q1, KCDIM*NSP);
    k_stats_fin<<<NB, 256>>>(KCDIM*NSP, 0);
    // 5. f_pixel conv2 (GN+relu of q1 fused into load) + stats
    k_conv<<<dim3(128, 1, NB), 256>>>(fp_w2, q1, 0, fp_g1, fp_b1, 128, nullptr, q2, 128, 128);
    k_stats_part<<<dim3(256, NB), 256>>>(q2, KCDIM*NSP);
    k_stats_fin<<<NB, 256>>>(KCDIM*NSP, 1);
    // 6. attention (GN+relu of q2 fused into load)
    k_attn<<<dim3(128, NB), 128, attn_smem>>>(fp_g2, fp_b2);
    // 7. f_up conv (raw att in) + stats
    k_conv<<<dim3(128, 2, NB), 256>>>(fu_w, att, -1, nullptr, nullptr, 128, nullptr, up, 128, 256);
    k_stats_part<<<dim3(256, NB), 256>>>(up, CDIM*NSP);
    k_stats_fin<<<NB, 256>>>(CDIM*NSP, 2);
    // 8. fuse conv: [GN+relu(up) ; feats] -> d_out raw
    k_conv<<<dim3(128, 2, NB), 256>>>(cb_w, up, 2, fu_g, fu_b, 256, feats, out, 512, 256);
    k_stats_part<<<dim3(256, NB), 256>>>(out, CDIM*NSP);
    k_stats_fin<<<NB, 256>>>(CDIM*NSP, 3);
    // 9. final GN + relu in place
    k_gnfinal<<<(NB*CDIM*NSP/4)/256, 256>>>(out, cb_g, cb_b);
}

// round 2
// speedup vs baseline: 1.8154x; 1.8154x over previous
#include <cuda_runtime.h>
#include <cstdint>

#define NB 8
#define NSP 16384
#define NCLS 21
#define CDIM 256
#define KCDIM 128
#define EPS_GN 1e-5f

// ----------------------------- scratch (device globals, no allocation) -----
__device__ float  g_probs[(size_t)NB*NCLS*NSP];
__device__ float  g_ctx  [NB*CDIM*NCLS];
__device__ float  g_kmat [NB*KCDIM*NCLS];
__device__ float  g_vmat [NB*KCDIM*NCLS];
__device__ float  g_q1   [(size_t)NB*KCDIM*NSP];
__device__ float  g_q2   [(size_t)NB*KCDIM*NSP];
__device__ float  g_att  [(size_t)NB*KCDIM*NSP];
__device__ float  g_up   [(size_t)NB*CDIM*NSP];
__device__ float2 g_part [NB*256];
__device__ float2 g_stats[4*NB];   // 0=q1 1=q2 2=up 3=out

__device__ __forceinline__ uint32_t f2tf(float v) {
    uint32_t u;
    asm("cvt.rna.tf32.f32 %0, %1;" : "=r"(u) : "f"(v));
    return u;
}

// ----------------------------- probs: bilinear(align_corners) + softmax ----
__global__ __launch_bounds__(256) void k_probs(const float* __restrict__ aux)
{
    int b = blockIdx.x / NCLS, k = blockIdx.x % NCLS;
    const float* src = aux + ((size_t)b*NCLS + k)*64*64;
    float* dst = g_probs + ((size_t)b*NCLS + k)*NSP;
    int tid = threadIdx.x;
    __shared__ float red[256];
    __shared__ float bc;
    const float sc = 63.f/127.f;

    float mx = -3.4e38f;
    for (int n = tid; n < NSP; n += 256) {
        int y = n >> 7, x = n & 127;
        float sy = y*sc, sx = x*sc;
        int y0 = (int)sy, x0 = (int)sx;
        float fy = sy - (float)y0, fx = sx - (float)x0;
        int y1 = min(y0+1, 63), x1 = min(x0+1, 63);
        float a00 = src[y0*64+x0], a01 = src[y0*64+x1];
        float a10 = src[y1*64+x0], a11 = src[y1*64+x1];
        float top = a00 + (a01-a00)*fx;
        float bot = a10 + (a11-a10)*fx;
        float v = top + (bot-top)*fy;
        dst[n] = v;
        mx = fmaxf(mx, v);
    }
    red[tid] = mx; __syncthreads();
    for (int s = 128; s > 0; s >>= 1) { if (tid < s) red[tid] = fmaxf(red[tid], red[tid+s]); __syncthreads(); }
    if (tid == 0) bc = red[0];
    __syncthreads();
    mx = bc;

    float sum = 0.f;
    for (int n = tid; n < NSP; n += 256) {
        float e = __expf(dst[n] - mx);
        dst[n] = e;
        sum += e;
    }
    __syncthreads();
    red[tid] = sum; __syncthreads();
    for (int s = 128; s > 0; s >>= 1) { if (tid < s) red[tid] += red[tid+s]; __syncthreads(); }
    if (tid == 0) bc = 1.f / red[0];
    __syncthreads();
    float inv = bc;
    for (int n = tid; n < NSP; n += 256) dst[n] *= inv;
}

// ----------------------------- ctx = probs @ feats^T : [b,256,21] ----------
__global__ __launch_bounds__(256) void k_ctx(const float* __restrict__ feats)
{
    __shared__ float p_s[NCLS*128];
    __shared__ float f_s[64*129];
    int b = blockIdx.y, c0 = blockIdx.x * 64;
    int tid = threadIdx.x;
    int tx = tid & 63, ty = tid >> 6;
    float acc[6] = {0,0,0,0,0,0};

    for (int k0 = 0; k0 < NSP; k0 += 128) {
        for (int e = tid; e < NCLS*128; e += 256) {
            int m = e >> 7, kk = e & 127;
            p_s[e] = g_probs[((size_t)b*NCLS + m)*NSP + k0 + kk];
        }
        for (int e = tid; e < 64*128; e += 256) {
            int r = e >> 7, kk = e & 127;
            f_s[r*129 + kk] = feats[((size_t)b*CDIM + c0 + r)*NSP + k0 + kk];
        }
        __syncthreads();
        for (int kk = 0; kk < 128; kk++) {
            float fv = f_s[tx*129 + kk];
            #pragma unroll
            for (int i = 0; i < 6; i++) {
                int m = ty + 4*i;
                if (m < NCLS) acc[i] += p_s[m*128 + kk] * fv;
            }
        }
        __syncthreads();
    }
    #pragma unroll
    for (int i = 0; i < 6; i++) {
        int m = ty + 4*i;
        if (m < NCLS) g_ctx[((size_t)b*CDIM + c0 + tx)*NCLS + m] = acc[i];
    }
}

// ----------------------------- tiny object branch: k,v [b,128,21] ----------
__global__ __launch_bounds__(256) void k_small(
    const float* __restrict__ fo_w1, const float* __restrict__ fo_g1, const float* __restrict__ fo_b1,
    const float* __restrict__ fo_w2, const float* __restrict__ fo_g2, const float* __restrict__ fo_b2,
    const float* __restrict__ fd_w,  const float* __restrict__ fd_g,  const float* __restrict__ fd_b)
{
    __shared__ float ctx_s[CDIM*NCLS];
    __shared__ float t_s[KCDIM*NCLS];
    __shared__ float u_s[KCDIM*NCLS];
    __shared__ float red[256];
    __shared__ float red2[256];
    __shared__ float2 mv;
    int b = blockIdx.x, tid = threadIdx.x;

    for (int e = tid; e < CDIM*NCLS; e += 256) ctx_s[e] = g_ctx[(size_t)b*CDIM*NCLS + e];
    __syncthreads();

    #define SMALL_GN(buf, gam, bet)                                                         \
    {                                                                                       \
        float s = 0.f, q = 0.f;                                                             \
        for (int e = tid; e < KCDIM*NCLS; e += 256) { float v = buf[e]; s += v; q += v*v; } \
        red[tid] = s; red2[tid] = q; __syncthreads();                                       \
        for (int st = 128; st > 0; st >>= 1) {                                              \
            if (tid < st) { red[tid] += red[tid+st]; red2[tid] += red2[tid+st]; }           \
            __syncthreads();                                                                \
        }                                                                                   \
        if (tid == 0) {                                                                     \
            float m = red[0] / (KCDIM*NCLS);                                                \
            float var = red2[0] / (KCDIM*NCLS) - m*m;                                       \
            mv.x = m; mv.y = rsqrtf(var + EPS_GN);                                          \
        }                                                                                   \
        __syncthreads();                                                                    \
        float m = mv.x, r = mv.y;                                                           \
        for (int e = tid; e < KCDIM*NCLS; e += 256) {                                       \
            int o = e / NCLS;                                                               \
            float v = (buf[e] - m) * r * gam[o] + bet[o];                                   \
            buf[e] = fmaxf(v, 0.f);                                                         \
        }                                                                                   \
        __syncthreads();                                                                    \
    }

    for (int e = tid; e < KCDIM*NCLS; e += 256) {
        int o = e / NCLS, kk = e % NCLS;
        float s = 0.f;
        for (int c = 0; c < CDIM; c++) s += fo_w1[o*CDIM + c] * ctx_s[c*NCLS + kk];
        t_s[e] = s;
    }
    __syncthreads();
    SMALL_GN(t_s, fo_g1, fo_b1)
    for (int e = tid; e < KCDIM*NCLS; e += 256) {
        int o = e / NCLS, kk = e % NCLS;
        float s = 0.f;
        for (int c = 0; c < KCDIM; c++) s += fo_w2[o*KCDIM + c] * t_s[c*NCLS + kk];
        u_s[e] = s;
    }
    __syncthreads();
    SMALL_GN(u_s, fo_g2, fo_b2)
    for (int e = tid; e < KCDIM*NCLS; e += 256) g_kmat[(size_t)b*KCDIM*NCLS + e] = u_s[e];
    __syncthreads();
    for (int e = tid; e < KCDIM*NCLS; e += 256) {
        int o = e / NCLS, kk = e % NCLS;
        float s = 0.f;
        for (int c = 0; c < CDIM; c++) s += fd_w[o*CDIM + c] * ctx_s[c*NCLS + kk];
        t_s[e] = s;
    }
    __syncthreads();
    SMALL_GN(t_s, fd_g, fd_b)
    for (int e = tid; e < KCDIM*NCLS; e += 256) g_vmat[(size_t)b*KCDIM*NCLS + e] = t_s[e];
    #undef SMALL_GN
}

// ----------------------------- tensor-core conv GEMM (tf32 mma) ------------
// Y[b,o,n] = sum_k W[o,k] * X[b,k,n]; GN+relu fused on Xa loads (k < Ka),
// raw Xb for k >= Ka (concat). Per-block GN partials of Y written to g_part.
// Tile 128x128xK, BK=16, 8 warps of 64x32 (4x4 m16n8k8 tf32 mma tiles).
#define PITCH 136
__global__ __launch_bounds__(256) void k_conv_tc(
    const float* __restrict__ W, const float* __restrict__ Xa,
    int stats_stage, const float* __restrict__ ga, const float* __restrict__ ba,
    int Ka, const float* __restrict__ Xb,
    float* __restrict__ Y, int K, int O)
{
    __shared__ uint32_t As[2][16][PITCH];
    __shared__ uint32_t Bs[2][16][PITCH];
    __shared__ float red[256];
    __shared__ float red2[256];

    int tid = threadIdx.x;
    int lane = tid & 31, wid = tid >> 5;
    int wm = (wid >> 2) * 64, wn = (wid & 3) * 32;
    int b = blockIdx.z;
    int n0 = blockIdx.x * 128, o0 = blockIdx.y * 128;

    float mean = 0.f, rstd = 0.f;
    if (stats_stage >= 0) { float2 st = g_stats[stats_stage*NB + b]; mean = st.x; rstd = st.y; }

    // loader indices
    int a_o  = tid >> 2;         // 0..63
    int a_k4 = (tid & 3) * 4;    // 0,4,8,12
    int b_k  = tid >> 4;         // 0..15
    int b_n  = (tid & 15) * 8;   // 0..120

    float acc[4][4][4];
    #pragma unroll
    for (int i = 0; i < 4; i++)
        #pragma unroll
        for (int j = 0; j < 4; j++)
            #pragma unroll
            for (int r = 0; r < 4; r++) acc[i][j][r] = 0.f;

    float4 ra0, ra1, rb0, rb1;
    float gk = 1.f, bk = 0.f;
    bool dogn = false;

    // ---- load helpers (inlined via lambdas) ----
    auto LOAD = [&](int k0) {
        ra0 = *(const float4*)&W[(size_t)(o0 + a_o)*K + k0 + a_k4];
        ra1 = *(const float4*)&W[(size_t)(o0 + 64 + a_o)*K + k0 + a_k4];
        int k = k0 + b_k;
        const float* src;
        if (k < Ka) src = &Xa[((size_t)b*Ka + k)*NSP + n0 + b_n];
        else        src = &Xb[((size_t)b*(K - Ka) + (k - Ka))*NSP + n0 + b_n];
        rb0 = *(const float4*)src;
        rb1 = *(const float4*)(src + 4);
        dogn = (stats_stage >= 0) && (k < Ka);
        if (dogn) { gk = ga[k]; bk = ba[k]; }
    };
    auto STORE = [&](int buf) {
        As[buf][a_k4+0][a_o] = f2tf(ra0.x);
        As[buf][a_k4+1][a_o] = f2tf(ra0.y);
        As[buf][a_k4+2][a_o] = f2tf(ra0.z);
        As[buf][a_k4+3][a_o] = f2tf(ra0.w);
        As[buf][a_k4+0][a_o+64] = f2tf(ra1.x);
        As[buf][a_k4+1][a_o+64] = f2tf(ra1.y);
        As[buf][a_k4+2][a_o+64] = f2tf(ra1.z);
        As[buf][a_k4+3][a_o+64] = f2tf(ra1.w);
        float v[8] = {rb0.x, rb0.y, rb0.z, rb0.w, rb1.x, rb1.y, rb1.z, rb1.w};
        #pragma unroll
        for (int j = 0; j < 8; j++) {
            float x = v[j];
            if (dogn) x = fmaxf((x - mean)*rstd*gk + bk, 0.f);
            Bs[buf][b_k][b_n + j] = f2tf(x);
        }
    };
    auto COMPUTE = [&](int buf) {
        #pragma unroll
        for (int ks = 0; ks < 2; ks++) {
            int kb = ks * 8;
            int row = lane >> 2, kq = lane & 3;
            uint32_t Af[4][4];
            #pragma unroll
            for (int mt = 0; mt < 4; mt++) {
                int m = wm + mt*16 + row;
                Af[mt][0] = As[buf][kb+kq  ][m];
                Af[mt][1] = As[buf][kb+kq  ][m+8];
                Af[mt][2] = As[buf][kb+kq+4][m];
                Af[mt][3] = As[buf][kb+kq+4][m+8];
            }
            uint32_t Bf[4][2];
            #pragma unroll
            for (int nt = 0; nt < 4; nt++) {
                int n = wn + nt*8 + row;
                Bf[nt][0] = Bs[buf][kb+kq  ][n];
                Bf[nt][1] = Bs[buf][kb+kq+4][n];
            }
            #pragma unroll
            for (int mt = 0; mt < 4; mt++)
                #pragma unroll
                for (int nt = 0; nt < 4; nt++) {
                    float* c = acc[mt][nt];
                    asm volatile(
                        "mma.sync.aligned.m16n8k8.row.col.f32.tf32.tf32.f32 "
                        "{%0,%1,%2,%3}, {%4,%5,%6,%7}, {%8,%9}, {%0,%1,%2,%3};"
                        : "+f"(c[0]), "+f"(c[1]), "+f"(c[2]), "+f"(c[3])
                        : "r"(Af[mt][0]), "r"(Af[mt][1]), "r"(Af[mt][2]), "r"(Af[mt][3]),
                          "r"(Bf[nt][0]), "r"(Bf[nt][1]));
                }
        }
    };

    int KT = K >> 4;
    LOAD(0);
    STORE(0);
    __syncthreads();
    for (int kt = 0; kt < KT; kt++) {
        int cur = kt & 1;
        if (kt + 1 < KT) LOAD((kt + 1) << 4);
        COMPUTE(cur);
        __syncthreads();
        if (kt + 1 < KT) {
            STORE(1 - cur);
            __syncthreads();
        }
    }

    // ---- epilogue: store C + per-block GN partial sums ----
    float sum = 0.f, sq = 0.f;
    #pragma unroll
    for (int mt = 0; mt < 4; mt++) {
        int row = o0 + wm + mt*16 + (lane >> 2);
        #pragma unroll
        for (int nt = 0; nt < 4; nt++) {
            float* c = acc[mt][nt];
            int col = n0 + wn + nt*8 + (lane & 3)*2;
            float2 v01 = make_float2(c[0], c[1]);
            float2 v23 = make_float2(c[2], c[3]);
            *(float2*)&Y[((size_t)b*O + row    )*NSP + col] = v01;
            *(float2*)&Y[((size_t)b*O + row + 8)*NSP + col] = v23;
            sum += c[0]+c[1]+c[2]+c[3];
            sq  += c[0]*c[0]+c[1]*c[1]+c[2]*c[2]+c[3]*c[3];
        }
    }
    red[tid] = sum; red2[tid] = sq;
    __syncthreads();
    for (int st = 128; st > 0; st >>= 1) {
        if (tid < st) { red[tid] += red[tid+st]; red2[tid] += red2[tid+st]; }
        __syncthreads();
    }
    if (tid == 0) {
        int pid = blockIdx.y * gridDim.x + blockIdx.x;
        g_part[b*256 + pid] = make_float2(red[0], red2[0]);
    }
}

// ----------------------------- GN stats finalize ---------------------------
__global__ __launch_bounds__(256) void k_stats_fin(int CN, int stage, int npart)
{
    int b = blockIdx.x, tid = threadIdx.x;
    __shared__ float red[256];
    __shared__ float red2[256];
    float2 v = (tid < npart) ? g_part[b*256 + tid] : make_float2(0.f, 0.f);
    red[tid] = v.x; red2[tid] = v.y; __syncthreads();
    for (int st = 128; st > 0; st >>= 1) {
        if (tid < st) { red[tid] += red[tid+st]; red2[tid] += red2[tid+st]; }
        __syncthreads();
    }
    if (tid == 0) {
        float m = red[0] / (float)CN;
        float var = red2[0] / (float)CN - m*m;
        g_stats[stage*NB + b] = make_float2(m, rsqrtf(var + EPS_GN));
    }
}

// ----------------------------- attention -----------------------------------
__global__ __launch_bounds__(128) void k_attn(const float* __restrict__ g2, const float* __restrict__ b2)
{
    extern __shared__ float sm[];
    float* q_s = sm;
    float* k_s = sm + KCDIM*128;
    float* v_s = k_s + KCDIM*NCLS;
    int b = blockIdx.y, n0 = blockIdx.x * 128;
    int tid = threadIdx.x;

    float2 st = g_stats[1*NB + b];
    float mean = st.x, rstd = st.y;

    for (int e = tid; e < KCDIM*128; e += 128) {
        int c = e >> 7, px = e & 127;
        float raw = g_q2[((size_t)b*KCDIM + c)*NSP + n0 + px];
        float v = (raw - mean)*rstd*g2[c] + b2[c];
        q_s[c*128 + px] = fmaxf(v, 0.f);
    }
    for (int e = tid; e < KCDIM*NCLS; e += 128) {
        k_s[e] = g_kmat[(size_t)b*KCDIM*NCLS + e];
        v_s[e] = g_vmat[(size_t)b*KCDIM*NCLS + e];
    }
    __syncthreads();

    int px = tid;
    float s[NCLS];
    #pragma unroll
    for (int kk = 0; kk < NCLS; kk++) s[kk] = 0.f;
    for (int c = 0; c < KCDIM; c++) {
        float qv = q_s[c*128 + px];
        #pragma unroll
        for (int kk = 0; kk < NCLS; kk++) s[kk] += qv * k_s[c*NCLS + kk];
    }
    const float scale = 0.0883883476483184f;
    float mx = -3.4e38f;
    #pragma unroll
    for (int kk = 0; kk < NCLS; kk++) { s[kk] *= scale; mx = fmaxf(mx, s[kk]); }
    float ssum = 0.f;
    #pragma unroll
    for (int kk = 0; kk < NCLS; kk++) { s[kk] = __expf(s[kk] - mx); ssum += s[kk]; }
    float inv = 1.f / ssum;
    #pragma unroll
    for (int kk = 0; kk < NCLS; kk++) s[kk] *= inv;

    for (int c = 0; c < KCDIM; c++) {
        float a = 0.f;
        #pragma unroll
        for (int kk = 0; kk < NCLS; kk++) a += s[kk] * v_s[c*NCLS + kk];
        g_att[((size_t)b*KCDIM + c)*NSP + n0 + px] = a;
    }
}

// ----------------------------- final GN + relu on d_out --------------------
__global__ __launch_bounds__(256) void k_gnfinal(float* __restrict__ Y,
                                                 const float* __restrict__ g,
                                                 const float* __restrict__ bb)
{
    size_t e = ((size_t)blockIdx.x*256 + threadIdx.x)*4;
    int b = (int)(e / ((size_t)CDIM*NSP));
    int c = (int)((e / NSP) & (CDIM-1));
    float2 st = g_stats[3*NB + b];
    float m = st.x, r = st.y;
    float gm = g[c], bt = bb[c];
    float4 v = *(float4*)&Y[e];
    v.x = fmaxf((v.x - m)*r*gm + bt, 0.f);
    v.y = fmaxf((v.y - m)*r*gm + bt, 0.f);
    v.z = fmaxf((v.z - m)*r*gm + bt, 0.f);
    v.w = fmaxf((v.w - m)*r*gm + bt, 0.f);
    *(float4*)&Y[e] = v;
}

// ----------------------------- host ----------------------------------------
extern "C" void kernel_launch(void* const* d_in, const int* in_sizes, int n_in,
                              void* d_out, int out_size)
{
    const float* feats   = (const float*)d_in[0];
    const float* out_aux = (const float*)d_in[1];
    const float* fp_w1 = (const float*)d_in[2];
    const float* fp_g1 = (const float*)d_in[3];
    const float* fp_b1 = (const float*)d_in[4];
    const float* fp_w2 = (const float*)d_in[5];
    const float* fp_g2 = (const float*)d_in[6];
    const float* fp_b2 = (const float*)d_in[7];
    const float* fo_w1 = (const float*)d_in[8];
    const float* fo_g1 = (const float*)d_in[9];
    const float* fo_b1 = (const float*)d_in[10];
    const float* fo_w2 = (const float*)d_in[11];
    const float* fo_g2 = (const float*)d_in[12];
    const float* fo_b2 = (const float*)d_in[13];
    const float* fd_w  = (const float*)d_in[14];
    const float* fd_g  = (const float*)d_in[15];
    const float* fd_b  = (const float*)d_in[16];
    const float* fu_w  = (const float*)d_in[17];
    const float* fu_g  = (const float*)d_in[18];
    const float* fu_b  = (const float*)d_in[19];
    const float* cb_w  = (const float*)d_in[20];
    const float* cb_g  = (const float*)d_in[21];
    const float* cb_b  = (const float*)d_in[22];
    float* out = (float*)d_out;

    void* p;
    cudaGetSymbolAddress(&p, g_q1);  float* q1  = (float*)p;
    cudaGetSymbolAddress(&p, g_q2);  float* q2  = (float*)p;
    cudaGetSymbolAddress(&p, g_att); float* att = (float*)p;
    cudaGetSymbolAddress(&p, g_up);  float* up  = (float*)p;

    const int attn_smem = (KCDIM*128 + 2*KCDIM*NCLS)*4;
    cudaFuncSetAttribute(k_attn, cudaFuncAttributeMaxDynamicSharedMemorySize, attn_smem);

    // 1. probs (interp + softmax)
    k_probs<<<NB*NCLS, 256>>>(out_aux);
    // 2. ctx gather
    k_ctx<<<dim3(4, NB), 256>>>(feats);
    // 3. tiny object branch -> k,v
    k_small<<<NB, 256>>>(fo_w1, fo_g1, fo_b1, fo_w2, fo_g2, fo_b2, fd_w, fd_g, fd_b);
    // 4. f_pixel conv1 (raw feats in), fused stats partials
    k_conv_tc<<<dim3(128, 1, NB), 256>>>(fp_w1, feats, -1, nullptr, nullptr, 256, nullptr, q1, 256, 128);
    k_stats_fin<<<NB, 256>>>(KCDIM*NSP, 0, 128);
    // 5. f_pixel conv2 (GN+relu of q1 fused into load)
    k_conv_tc<<<dim3(128, 1, NB), 256>>>(fp_w2, q1, 0, fp_g1, fp_b1, 128, nullptr, q2, 128, 128);
    k_stats_fin<<<NB, 256>>>(KCDIM*NSP, 1, 128);
    // 6. attention (GN+relu of q2 fused into load)
    k_attn<<<dim3(128, NB), 128, attn_smem>>>(fp_g2, fp_b2);
    // 7. f_up conv (raw att in)
    k_conv_tc<<<dim3(128, 2, NB), 256>>>(fu_w, att, -1, nullptr, nullptr, 128, nullptr, up, 128, 256);
    k_stats_fin<<<NB, 256>>>(CDIM*NSP, 2, 256);
    // 8. fuse conv: [GN+relu(up) ; feats] -> d_out raw
    k_conv_tc<<<dim3(128, 2, NB), 256>>>(cb_w, up, 2, fu_g, fu_b, 256, feats, out, 512, 256);
    k_stats_fin<<<NB, 256>>>(CDIM*NSP, 3, 256);
    // 9. final GN + relu in place
    k_gnfinal<<<(NB*CDIM*NSP/4)/256, 256>>>(out, cb_g, cb_b);
}

// round 4
// speedup vs baseline: 3.9643x; 2.1837x over previous
#include <cuda_runtime.h>
#include <cstdint>

#define NB 8
#define NSP 16384
#define NCLS 21
#define CDIM 256
#define KCDIM 128
#define EPS_GN 1e-5f
#define CTX_SLICES 16

// ----------------------------- scratch (device globals, no allocation) -----
__device__ float  g_probs[(size_t)NB*NCLS*NSP];
__device__ float  g_ctx  [NB*CDIM*NCLS];
__device__ float  g_ctxp [(size_t)CTX_SLICES*NB*CDIM*NCLS];
__device__ float  g_kmat [NB*KCDIM*NCLS];
__device__ float  g_vmat [NB*KCDIM*NCLS];
__device__ float  g_q1   [(size_t)NB*KCDIM*NSP];
__device__ float  g_q2   [(size_t)NB*KCDIM*NSP];
__device__ float  g_att  [(size_t)NB*KCDIM*NSP];
__device__ float  g_up   [(size_t)NB*CDIM*NSP];
__device__ float2 g_part [NB*256];
__device__ float2 g_stats[4*NB];   // 0=q1 1=q2 2=up 3=out

__device__ __forceinline__ uint32_t f2tf(float v) {
    uint32_t u;
    asm("cvt.rna.tf32.f32 %0, %1;" : "=r"(u) : "f"(v));
    return u;
}

// ----------------------------- probs: bilinear(align_corners) + softmax ----
__global__ __launch_bounds__(256) void k_probs(const float* __restrict__ aux)
{
    int b = blockIdx.x / NCLS, k = blockIdx.x % NCLS;
    const float* src = aux + ((size_t)b*NCLS + k)*64*64;
    float* dst = g_probs + ((size_t)b*NCLS + k)*NSP;
    int tid = threadIdx.x;
    __shared__ float red[256];
    __shared__ float bc;
    const float sc = 63.f/127.f;

    float mx = -3.4e38f;
    for (int n = tid; n < NSP; n += 256) {
        int y = n >> 7, x = n & 127;
        float sy = y*sc, sx = x*sc;
        int y0 = (int)sy, x0 = (int)sx;
        float fy = sy - (float)y0, fx = sx - (float)x0;
        int y1 = min(y0+1, 63), x1 = min(x0+1, 63);
        float a00 = src[y0*64+x0], a01 = src[y0*64+x1];
        float a10 = src[y1*64+x0], a11 = src[y1*64+x1];
        float top = a00 + (a01-a00)*fx;
        float bot = a10 + (a11-a10)*fx;
        float v = top + (bot-top)*fy;
        dst[n] = v;
        mx = fmaxf(mx, v);
    }
    red[tid] = mx; __syncthreads();
    for (int s = 128; s > 0; s >>= 1) { if (tid < s) red[tid] = fmaxf(red[tid], red[tid+s]); __syncthreads(); }
    if (tid == 0) bc = red[0];
    __syncthreads();
    mx = bc;

    float sum = 0.f;
    for (int n = tid; n < NSP; n += 256) {
        float e = __expf(dst[n] - mx);
        dst[n] = e;
        sum += e;
    }
    __syncthreads();
    red[tid] = sum; __syncthreads();
    for (int s = 128; s > 0; s >>= 1) { if (tid < s) red[tid] += red[tid+s]; __syncthreads(); }
    if (tid == 0) bc = 1.f / red[0];
    __syncthreads();
    float inv = bc;
    for (int n = tid; n < NSP; n += 256) dst[n] *= inv;
}

// -------------- ctx partials: split-K over 16 slices -----------------------
__global__ __launch_bounds__(256) void k_ctx2(const float* __restrict__ feats)
{
    __shared__ float p_s[NCLS*128];
    __shared__ float f_s[64*129];
    int b = blockIdx.y, c0 = blockIdx.x * 64, ksl = blockIdx.z;
    int tid = threadIdx.x;
    int tx = tid & 63, ty = tid >> 6;
    float acc[6] = {0,0,0,0,0,0};

    int kbeg = ksl * (NSP / CTX_SLICES);
    int kend = kbeg + (NSP / CTX_SLICES);
    for (int k0 = kbeg; k0 < kend; k0 += 128) {
        for (int e = tid; e < NCLS*128; e += 256) {
            int m = e >> 7, kk = e & 127;
            p_s[e] = g_probs[((size_t)b*NCLS + m)*NSP + k0 + kk];
        }
        for (int e = tid; e < 64*128; e += 256) {
            int r = e >> 7, kk = e & 127;
            f_s[r*129 + kk] = feats[((size_t)b*CDIM + c0 + r)*NSP + k0 + kk];
        }
        __syncthreads();
        for (int kk = 0; kk < 128; kk++) {
            float fv = f_s[tx*129 + kk];
            #pragma unroll
            for (int i = 0; i < 6; i++) {
                int m = ty + 4*i;
                if (m < NCLS) acc[i] += p_s[m*128 + kk] * fv;
            }
        }
        __syncthreads();
    }
    #pragma unroll
    for (int i = 0; i < 6; i++) {
        int m = ty + 4*i;
        if (m < NCLS)
            g_ctxp[((size_t)ksl*NB + b)*CDIM*NCLS + (size_t)(c0 + tx)*NCLS + m] = acc[i];
    }
}

__global__ __launch_bounds__(256) void k_ctx_red()
{
    int idx = blockIdx.x*256 + threadIdx.x;
    if (idx >= NB*CDIM*NCLS) return;
    float s = 0.f;
    #pragma unroll
    for (int sl = 0; sl < CTX_SLICES; sl++)
        s += g_ctxp[(size_t)sl*NB*CDIM*NCLS + idx];
    g_ctx[idx] = s;
}

// ----------------------------- tiny object branch: k,v [b,128,21] ----------
__global__ __launch_bounds__(256) void k_small(
    const float* __restrict__ fo_w1, const float* __restrict__ fo_g1, const float* __restrict__ fo_b1,
    const float* __restrict__ fo_w2, const float* __restrict__ fo_g2, const float* __restrict__ fo_b2,
    const float* __restrict__ fd_w,  const float* __restrict__ fd_g,  const float* __restrict__ fd_b)
{
    __shared__ float ctx_s[CDIM*NCLS];
    __shared__ float t_s[KCDIM*NCLS];
    __shared__ float u_s[KCDIM*NCLS];
    __shared__ float red[256];
    __shared__ float red2[256];
    __shared__ float2 mv;
    int b = blockIdx.x, tid = threadIdx.x;

    for (int e = tid; e < CDIM*NCLS; e += 256) ctx_s[e] = g_ctx[(size_t)b*CDIM*NCLS + e];
    __syncthreads();

    #define SMALL_GN(buf, gam, bet)                                                         \
    {                                                                                       \
        float s = 0.f, q = 0.f;                                                             \
        for (int e = tid; e < KCDIM*NCLS; e += 256) { float v = buf[e]; s += v; q += v*v; } \
        red[tid] = s; red2[tid] = q; __syncthreads();                                       \
        for (int st = 128; st > 0; st >>= 1) {                                              \
            if (tid < st) { red[tid] += red[tid+st]; red2[tid] += red2[tid+st]; }           \
            __syncthreads();                                                                \
        }                                                                                   \
        if (tid == 0) {                                                                     \
            float m = red[0] / (KCDIM*NCLS);                                                \
            float var = red2[0] / (KCDIM*NCLS) - m*m;                                       \
            mv.x = m; mv.y = rsqrtf(var + EPS_GN);                                          \
        }                                                                                   \
        __syncthreads();                                                                    \
        float m = mv.x, r = mv.y;                                                           \
        for (int e = tid; e < KCDIM*NCLS; e += 256) {                                       \
            int o = e / NCLS;                                                               \
            float v = (buf[e] - m) * r * gam[o] + bet[o];                                   \
            buf[e] = fmaxf(v, 0.f);                                                         \
        }                                                                                   \
        __syncthreads();                                                                    \
    }

    for (int e = tid; e < KCDIM*NCLS; e += 256) {
        int o = e / NCLS, kk = e % NCLS;
        float s = 0.f;
        for (int c = 0; c < CDIM; c++) s += fo_w1[o*CDIM + c] * ctx_s[c*NCLS + kk];
        t_s[e] = s;
    }
    __syncthreads();
    SMALL_GN(t_s, fo_g1, fo_b1)
    for (int e = tid; e < KCDIM*NCLS; e += 256) {
        int o = e / NCLS, kk = e % NCLS;
        float s = 0.f;
        for (int c = 0; c < KCDIM; c++) s += fo_w2[o*KCDIM + c] * t_s[c*NCLS + kk];
        u_s[e] = s;
    }
    __syncthreads();
    SMALL_GN(u_s, fo_g2, fo_b2)
    for (int e = tid; e < KCDIM*NCLS; e += 256) g_kmat[(size_t)b*KCDIM*NCLS + e] = u_s[e];
    __syncthreads();
    for (int e = tid; e < KCDIM*NCLS; e += 256) {
        int o = e / NCLS, kk = e % NCLS;
        float s = 0.f;
        for (int c = 0; c < CDIM; c++) s += fd_w[o*CDIM + c] * ctx_s[c*NCLS + kk];
        t_s[e] = s;
    }
    __syncthreads();
    SMALL_GN(t_s, fd_g, fd_b)
    for (int e = tid; e < KCDIM*NCLS; e += 256) g_vmat[(size_t)b*KCDIM*NCLS + e] = t_s[e];
    #undef SMALL_GN
}

// ----------------------------- tensor-core conv GEMM (tf32 mma) ------------
// Block tile 128(O) x 256(N), K-step 16. 8 warps = 2x4, warp tile 64x64.
// A packed uint2 (k, k+4) pairs: PA[2][8][132]; B plain float: PB[2][16][264].
// GN+relu fused on Xa loads (k < Ka), raw Xb for k >= Ka (concat case).
__global__ __launch_bounds__(256) void k_conv_tc(
    const float* __restrict__ W, const float* __restrict__ Xa,
    int stats_stage, const float* __restrict__ ga, const float* __restrict__ ba,
    int Ka, const float* __restrict__ Xb,
    float* __restrict__ Y, int K, int O)
{
    extern __shared__ float smf[];
    uint2* PA = (uint2*)smf;           // stage s: PA + s*1056  (8*132)
    float* PB = smf + 4224;            // stage s: PB + s*4224  (16*264)

    int tid = threadIdx.x;
    int lane = tid & 31, wid = tid >> 5;
    int wr = wid >> 2, wc = wid & 3;       // warp: (wr*64) x (wc*64)
    int b = blockIdx.z;
    int n0 = blockIdx.x * 256, o0 = blockIdx.y * 128;

    float mean = 0.f, rstd = 0.f;
    if (stats_stage >= 0) { float2 st = g_stats[stats_stage*NB + b]; mean = st.x; rstd = st.y; }

    int a_o = tid >> 1;            // 0..127 (O row)
    int a_h = tid & 1;             // which 8-k half
    int b_k = tid >> 4;            // 0..15 (k row)
    int b_nb = (tid & 15) * 4;     // n base within 64-chunk

    float acc[4][8][4];
    #pragma unroll
    for (int i = 0; i < 4; i++)
        #pragma unroll
        for (int j = 0; j < 8; j++)
            #pragma unroll
            for (int r = 0; r < 4; r++) acc[i][j][r] = 0.f;

    float4 ra0, ra1, rb[4];
    float gk = 1.f, bk = 0.f;
    bool dogn = false;

    auto LOAD = [&](int k0) {
        const float* wr_ = &W[(size_t)(o0 + a_o)*K + k0 + a_h*8];
        ra0 = *(const float4*)wr_;
        ra1 = *(const float4*)(wr_ + 4);
        int k = k0 + b_k;
        const float* src;
        if (k < Ka) src = &Xa[((size_t)b*Ka + k)*NSP + n0];
        else        src = &Xb[((size_t)b*(K - Ka) + (k - Ka))*NSP + n0];
        #pragma unroll
        for (int q = 0; q < 4; q++) rb[q] = *(const float4*)&src[b_nb + q*64];
        dogn = (stats_stage >= 0) && (k < Ka);
        if (dogn) { gk = ga[k]; bk = ba[k]; }
    };
    auto STORE = [&](int s) {
        uint2* pa = PA + s*1056;
        int i0 = a_h * 4;
        pa[(i0+0)*132 + a_o] = make_uint2(f2tf(ra0.x), f2tf(ra1.x));
        pa[(i0+1)*132 + a_o] = make_uint2(f2tf(ra0.y), f2tf(ra1.y));
        pa[(i0+2)*132 + a_o] = make_uint2(f2tf(ra0.z), f2tf(ra1.z));
        pa[(i0+3)*132 + a_o] = make_uint2(f2tf(ra0.w), f2tf(ra1.w));
        float* pb = PB + s*4224;
        #pragma unroll
        for (int q = 0; q < 4; q++) {
            float4 v = rb[q];
            if (dogn) {
                v.x = fmaxf((v.x - mean)*rstd*gk + bk, 0.f);
                v.y = fmaxf((v.y - mean)*rstd*gk + bk, 0.f);
                v.z = fmaxf((v.z - mean)*rstd*gk + bk, 0.f);
                v.w = fmaxf((v.w - mean)*rstd*gk + bk, 0.f);
            }
            float4 t;
            t.x = __uint_as_float(f2tf(v.x));
            t.y = __uint_as_float(f2tf(v.y));
            t.z = __uint_as_float(f2tf(v.z));
            t.w = __uint_as_float(f2tf(v.w));
            *(float4*)&pb[b_k*264 + b_nb + q*64] = t;
        }
    };
    auto COMPUTE = [&](int s) {
        uint2* pa = PA + s*1056;
        float* pb = PB + s*4224;
        int row4 = lane >> 2, kq = lane & 3;
        #pragma unroll
        for (int ks = 0; ks < 2; ks++) {
            uint32_t Af[4][4];
            #pragma unroll
            for (int mt = 0; mt < 4; mt++) {
                int m = wr*64 + mt*16 + row4;
                uint2 lo = pa[(ks*4 + kq)*132 + m];
                uint2 hi = pa[(ks*4 + kq)*132 + m + 8];
                Af[mt][0] = lo.x; Af[mt][1] = hi.x; Af[mt][2] = lo.y; Af[mt][3] = hi.y;
            }
            uint32_t Bf[8][2];
            #pragma unroll
            for (int nt = 0; nt < 8; nt++) {
                int n = wc*64 + nt*8 + row4;
                Bf[nt][0] = __float_as_uint(pb[(ks*8 + kq    )*264 + n]);
                Bf[nt][1] = __float_as_uint(pb[(ks*8 + kq + 4)*264 + n]);
            }
            #pragma unroll
            for (int mt = 0; mt < 4; mt++)
                #pragma unroll
                for (int nt = 0; nt < 8; nt++) {
                    float* c = acc[mt][nt];
                    asm volatile(
                        "mma.sync.aligned.m16n8k8.row.col.f32.tf32.tf32.f32 "
                        "{%0,%1,%2,%3}, {%4,%5,%6,%7}, {%8,%9}, {%0,%1,%2,%3};"
                        : "+f"(c[0]), "+f"(c[1]), "+f"(c[2]), "+f"(c[3])
                        : "r"(Af[mt][0]), "r"(Af[mt][1]), "r"(Af[mt][2]), "r"(Af[mt][3]),
                          "r"(Bf[nt][0]), "r"(Bf[nt][1]));
                }
        }
    };

    int KT = K >> 4;
    LOAD(0);
    STORE(0);
    __syncthreads();
    for (int kt = 0; kt < KT; kt++) {
        int cur = kt & 1;
        if (kt + 1 < KT) LOAD((kt + 1) << 4);
        COMPUTE(cur);
        if (kt + 1 < KT) STORE(1 - cur);
        __syncthreads();
    }

    // ---- epilogue: store C + per-block GN partial sums ----
    float sum = 0.f, sq = 0.f;
    int row4 = lane >> 2, c2 = (lane & 3)*2;
    #pragma unroll
    for (int mt = 0; mt < 4; mt++) {
        int row = o0 + wr*64 + mt*16 + row4;
        #pragma unroll
        for (int nt = 0; nt < 8; nt++) {
            float* c = acc[mt][nt];
            int col = n0 + wc*64 + nt*8 + c2;
            *(float2*)&Y[((size_t)b*O + row    )*NSP + col] = make_float2(c[0], c[1]);
            *(float2*)&Y[((size_t)b*O + row + 8)*NSP + col] = make_float2(c[2], c[3]);
            sum += c[0]+c[1]+c[2]+c[3];
            sq  += c[0]*c[0]+c[1]*c[1]+c[2]*c[2]+c[3]*c[3];
        }
    }
    float* red  = smf;
    float* red2 = smf + 256;
    red[tid] = sum; red2[tid] = sq;
    __syncthreads();
    for (int st = 128; st > 0; st >>= 1) {
        if (tid < st) { red[tid] += red[tid+st]; red2[tid] += red2[tid+st]; }
        __syncthreads();
    }
    if (tid == 0) {
        int pid = blockIdx.y * gridDim.x + blockIdx.x;
        g_part[b*256 + pid] = make_float2(red[0], red2[0]);
    }
}

// ----------------------------- GN stats finalize ---------------------------
__global__ __launch_bounds__(256) void k_stats_fin(int CN, int stage, int npart)
{
    int b = blockIdx.x, tid = threadIdx.x;
    __shared__ float red[256];
    __shared__ float red2[256];
    float2 v = (tid < npart) ? g_part[b*256 + tid] : make_float2(0.f, 0.f);
    red[tid] = v.x; red2[tid] = v.y; __syncthreads();
    for (int st = 128; st > 0; st >>= 1) {
        if (tid < st) { red[tid] += red[tid+st]; red2[tid] += red2[tid+st]; }
        __syncthreads();
    }
    if (tid == 0) {
        float m = red[0] / (float)CN;
        float var = red2[0] / (float)CN - m*m;
        g_stats[stage*NB + b] = make_float2(m, rsqrtf(var + EPS_GN));
    }
}

// ----------------------------- attention -----------------------------------
__global__ __launch_bounds__(128) void k_attn(const float* __restrict__ g2, const float* __restrict__ b2)
{
    extern __shared__ float sm[];
    float* q_s = sm;
    float* k_s = sm + KCDIM*128;
    float* v_s = k_s + KCDIM*NCLS;
    int b = blockIdx.y, n0 = blockIdx.x * 128;
    int tid = threadIdx.x;

    float2 st = g_stats[1*NB + b];
    float mean = st.x, rstd = st.y;

    for (int e = tid; e < KCDIM*128; e += 128) {
        int c = e >> 7, px = e & 127;
        float raw = g_q2[((size_t)b*KCDIM + c)*NSP + n0 + px];
        float v = (raw - mean)*rstd*g2[c] + b2[c];
        q_s[c*128 + px] = fmaxf(v, 0.f);
    }
    for (int e = tid; e < KCDIM*NCLS; e += 128) {
        k_s[e] = g_kmat[(size_t)b*KCDIM*NCLS + e];
        v_s[e] = g_vmat[(size_t)b*KCDIM*NCLS + e];
    }
    __syncthreads();

    int px = tid;
    float s[NCLS];
    #pragma unroll
    for (int kk = 0; kk < NCLS; kk++) s[kk] = 0.f;
    for (int c = 0; c < KCDIM; c++) {
        float qv = q_s[c*128 + px];
        #pragma unroll
        for (int kk = 0; kk < NCLS; kk++) s[kk] += qv * k_s[c*NCLS + kk];
    }
    const float scale = 0.0883883476483184f;
    float mx = -3.4e38f;
    #pragma unroll
    for (int kk = 0; kk < NCLS; kk++) { s[kk] *= scale; mx = fmaxf(mx, s[kk]); }
    float ssum = 0.f;
    #pragma unroll
    for (int kk = 0; kk < NCLS; kk++) { s[kk] = __expf(s[kk] - mx); ssum += s[kk]; }
    float inv = 1.f / ssum;
    #pragma unroll
    for (int kk = 0; kk < NCLS; kk++) s[kk] *= inv;

    for (int c = 0; c < KCDIM; c++) {
        float a = 0.f;
        #pragma unroll
        for (int kk = 0; kk < NCLS; kk++) a += s[kk] * v_s[c*NCLS + kk];
        g_att[((size_t)b*KCDIM + c)*NSP + n0 + px] = a;
    }
}

// ----------------------------- final GN + relu on d_out --------------------
__global__ __launch_bounds__(256) void k_gnfinal(float* __restrict__ Y,
                                                 const float* __restrict__ g,
                                                 const float* __restrict__ bb)
{
    size_t e = ((size_t)blockIdx.x*256 + threadIdx.x)*4;
    int b = (int)(e / ((size_t)CDIM*NSP));
    int c = (int)((e / NSP) & (CDIM-1));
    float2 st = g_stats[3*NB + b];
    float m = st.x, r = st.y;
    float gm = g[c], bt = bb[c];
    float4 v = *(float4*)&Y[e];
    v.x = fmaxf((v.x - m)*r*gm + bt, 0.f);
    v.y = fmaxf((v.y - m)*r*gm + bt, 0.f);
    v.z = fmaxf((v.z - m)*r*gm + bt, 0.f);
    v.w = fmaxf((v.w - m)*r*gm + bt, 0.f);
    *(float4*)&Y[e] = v;
}

// ----------------------------- host ----------------------------------------
extern "C" void kernel_launch(void* const* d_in, const int* in_sizes, int n_in,
                              void* d_out, int out_size)
{
    const float* feats   = (const float*)d_in[0];
    const float* out_aux = (const float*)d_in[1];
    const float* fp_w1 = (const float*)d_in[2];
    const float* fp_g1 = (const float*)d_in[3];
    const float* fp_b1 = (const float*)d_in[4];
    const float* fp_w2 = (const float*)d_in[5];
    const float* fp_g2 = (const float*)d_in[6];
    const float* fp_b2 = (const float*)d_in[7];
    const float* fo_w1 = (const float*)d_in[8];
    const float* fo_g1 = (const float*)d_in[9];
    const float* fo_b1 = (const float*)d_in[10];
    const float* fo_w2 = (const float*)d_in[11];
    const float* fo_g2 = (const float*)d_in[12];
    const float* fo_b2 = (const float*)d_in[13];
    const float* fd_w  = (const float*)d_in[14];
    const float* fd_g  = (const float*)d_in[15];
    const float* fd_b  = (const float*)d_in[16];
    const float* fu_w  = (const float*)d_in[17];
    const float* fu_g  = (const float*)d_in[18];
    const float* fu_b  = (const float*)d_in[19];
    const float* cb_w  = (const float*)d_in[20];
    const float* cb_g  = (const float*)d_in[21];
    const float* cb_b  = (const float*)d_in[22];
    float* out = (float*)d_out;

    void* p;
    cudaGetSymbolAddress(&p, g_q1);  float* q1  = (float*)p;
    cudaGetSymbolAddress(&p, g_q2);  float* q2  = (float*)p;
    cudaGetSymbolAddress(&p, g_att); float* att = (float*)p;
    cudaGetSymbolAddress(&p, g_up);  float* up  = (float*)p;

    const int attn_smem = (KCDIM*128 + 2*KCDIM*NCLS)*4;
    cudaFuncSetAttribute(k_attn, cudaFuncAttributeMaxDynamicSharedMemorySize, attn_smem);
    const int conv_smem = (4224 + 2*4224) * 4;   // A 2*1056 uint2 + B 2*4224 f = 50688 B
    cudaFuncSetAttribute(k_conv_tc, cudaFuncAttributeMaxDynamicSharedMemorySize, conv_smem);

    // 1. probs (interp + softmax)
    k_probs<<<NB*NCLS, 256>>>(out_aux);
    // 2. ctx gather: split-K partials + reduce
    k_ctx2<<<dim3(4, NB, CTX_SLICES), 256>>>(feats);
    k_ctx_red<<<(NB*CDIM*NCLS + 255)/256, 256>>>();
    // 3. tiny object branch -> k,v
    k_small<<<NB, 256>>>(fo_w1, fo_g1, fo_b1, fo_w2, fo_g2, fo_b2, fd_w, fd_g, fd_b);
    // 4. f_pixel conv1 (raw feats in), fused stats partials
    k_conv_tc<<<dim3(64, 1, NB), 256, conv_smem>>>(fp_w1, feats, -1, nullptr, nullptr, 256, nullptr, q1, 256, 128);
    k_stats_fin<<<NB, 256>>>(KCDIM*NSP, 0, 64);
    // 5. f_pixel conv2 (GN+relu of q1 fused into load)
    k_conv_tc<<<dim3(64, 1, NB), 256, conv_smem>>>(fp_w2, q1, 0, fp_g1, fp_b1, 128, nullptr, q2, 128, 128);
    k_stats_fin<<<NB, 256>>>(KCDIM*NSP, 1, 64);
    // 6. attention (GN+relu of q2 fused into load)
    k_attn<<<dim3(128, NB), 128, attn_smem>>>(fp_g2, fp_b2);
    // 7. f_up conv (raw att in)
    k_conv_tc<<<dim3(64, 2, NB), 256, conv_smem>>>(fu_w, att, -1, nullptr, nullptr, 128, nullptr, up, 128, 256);
    k_stats_fin<<<NB, 256>>>(CDIM*NSP, 2, 128);
    // 8. fuse conv: [GN+relu(up) ; feats] -> d_out raw
    k_conv_tc<<<dim3(64, 2, NB), 256, conv_smem>>>(cb_w, up, 2, fu_g, fu_b, 256, feats, out, 512, 256);
    k_stats_fin<<<NB, 256>>>(CDIM*NSP, 3, 128);
    // 9. final GN + relu in place
    k_gnfinal<<<(NB*CDIM*NSP/4)/256, 256>>>(out, cb_g, cb_b);
}

// round 5
// speedup vs baseline: 4.6294x; 1.1678x over previous
#include <cuda_runtime.h>
#include <cstdint>

#define NB 8
#define NSP 16384
#define NCLS 21
#define CDIM 256
#define KCDIM 128
#define EPS_GN 1e-5f
#define CTX_SLICES 16
#define SMELEM (KCDIM*NCLS)   // 2688

// ----------------------------- scratch (device globals, no allocation) -----
__device__ float  g_probs[(size_t)NB*NCLS*NSP];
__device__ float  g_ctx  [NB*CDIM*NCLS];
__device__ float  g_ctxp [(size_t)CTX_SLICES*NB*CDIM*NCLS];
__device__ float  g_sm1  [NB*SMELEM];
__device__ float  g_sm2  [NB*SMELEM];
__device__ float  g_kmat [NB*SMELEM];
__device__ float  g_vmat [NB*SMELEM];
__device__ float  g_q1   [(size_t)NB*KCDIM*NSP];
__device__ float  g_q2   [(size_t)NB*KCDIM*NSP];
__device__ float  g_att  [(size_t)NB*KCDIM*NSP];
__device__ float  g_up   [(size_t)NB*CDIM*NSP];
__device__ float2 g_part [NB*256];
__device__ float2 g_stats[4*NB];   // 0=q1 1=q2 2=up 3=out

__device__ __forceinline__ uint32_t f2tf(float v) {
    uint32_t u;
    asm("cvt.rna.tf32.f32 %0, %1;" : "=r"(u) : "f"(v));
    return u;
}

// ----------------------------- probs: bilinear(align_corners) + softmax ----
// single gmem write: 64 values/thread live in registers; src staged in smem.
__global__ __launch_bounds__(256) void k_probs(const float* __restrict__ aux)
{
    int b = blockIdx.x / NCLS, k = blockIdx.x % NCLS;
    const float* src = aux + ((size_t)b*NCLS + k)*64*64;
    float* dst = g_probs + ((size_t)b*NCLS + k)*NSP;
    int tid = threadIdx.x;
    __shared__ float s_src[4096];
    __shared__ float red[256];
    __shared__ float bc;
    const float sc = 63.f/127.f;

    for (int i = tid; i < 4096; i += 256) s_src[i] = src[i];
    __syncthreads();

    float v[64];
    float mx = -3.4e38f;
    #pragma unroll
    for (int i = 0; i < 64; i++) {
        int n = tid + i*256;
        int y = n >> 7, x = n & 127;
        float sy = y*sc, sx = x*sc;
        int y0 = (int)sy, x0 = (int)sx;
        float fy = sy - (float)y0, fx = sx - (float)x0;
        int y1 = min(y0+1, 63), x1 = min(x0+1, 63);
        float a00 = s_src[y0*64+x0], a01 = s_src[y0*64+x1];
        float a10 = s_src[y1*64+x0], a11 = s_src[y1*64+x1];
        float top = a00 + (a01-a00)*fx;
        float bot = a10 + (a11-a10)*fx;
        float t = top + (bot-top)*fy;
        v[i] = t;
        mx = fmaxf(mx, t);
    }
    red[tid] = mx; __syncthreads();
    for (int s = 128; s > 0; s >>= 1) { if (tid < s) red[tid] = fmaxf(red[tid], red[tid+s]); __syncthreads(); }
    if (tid == 0) bc = red[0];
    __syncthreads();
    mx = bc;

    float sum = 0.f;
    #pragma unroll
    for (int i = 0; i < 64; i++) { v[i] = __expf(v[i] - mx); sum += v[i]; }
    __syncthreads();
    red[tid] = sum; __syncthreads();
    for (int s = 128; s > 0; s >>= 1) { if (tid < s) red[tid] += red[tid+s]; __syncthreads(); }
    if (tid == 0) bc = 1.f / red[0];
    __syncthreads();
    float inv = bc;
    #pragma unroll
    for (int i = 0; i < 64; i++) dst[tid + i*256] = v[i] * inv;
}

// -------------- ctx partials: split-K over 16 slices -----------------------
__global__ __launch_bounds__(256) void k_ctx2(const float* __restrict__ feats)
{
    __shared__ float p_s[NCLS*128];
    __shared__ float f_s[64*129];
    int b = blockIdx.y, c0 = blockIdx.x * 64, ksl = blockIdx.z;
    int tid = threadIdx.x;
    int tx = tid & 63, ty = tid >> 6;
    float acc[6] = {0,0,0,0,0,0};

    int kbeg = ksl * (NSP / CTX_SLICES);
    int kend = kbeg + (NSP / CTX_SLICES);
    for (int k0 = kbeg; k0 < kend; k0 += 128) {
        for (int e = tid; e < NCLS*128; e += 256) {
            int m = e >> 7, kk = e & 127;
            p_s[e] = g_probs[((size_t)b*NCLS + m)*NSP + k0 + kk];
        }
        for (int e = tid; e < 64*128; e += 256) {
            int r = e >> 7, kk = e & 127;
            f_s[r*129 + kk] = feats[((size_t)b*CDIM + c0 + r)*NSP + k0 + kk];
        }
        __syncthreads();
        for (int kk = 0; kk < 128; kk++) {
            float fv = f_s[tx*129 + kk];
            #pragma unroll
            for (int i = 0; i < 6; i++) {
                int m = ty + 4*i;
                if (m < NCLS) acc[i] += p_s[m*128 + kk] * fv;
            }
        }
        __syncthreads();
    }
    #pragma unroll
    for (int i = 0; i < 6; i++) {
        int m = ty + 4*i;
        if (m < NCLS)
            g_ctxp[((size_t)ksl*NB + b)*CDIM*NCLS + (size_t)(c0 + tx)*NCLS + m] = acc[i];
    }
}

__global__ __launch_bounds__(256) void k_ctx_red()
{
    int idx = blockIdx.x*256 + threadIdx.x;
    if (idx >= NB*CDIM*NCLS) return;
    float s = 0.f;
    #pragma unroll
    for (int sl = 0; sl < CTX_SLICES; sl++)
        s += g_ctxp[(size_t)sl*NB*CDIM*NCLS + idx];
    g_ctx[idx] = s;
}

// -------------- object branch: warp-per-element GEMM -----------------------
// out[b][o*21+kk] = dot(W[o,0:K], src[b][c*21+kk], c=0..K-1)
__global__ __launch_bounds__(256) void k_sm_gemm(
    const float* __restrict__ W, const float* __restrict__ src,
    float* __restrict__ out, int K)
{
    int gw = blockIdx.x * 8 + (threadIdx.x >> 5);
    int lane = threadIdx.x & 31;
    if (gw >= NB*SMELEM) return;
    int b = gw / SMELEM;
    int r = gw - b*SMELEM;
    int o = r / NCLS, kk = r - o*NCLS;
    const float* wr = W + (size_t)o*K;
    const float* sr = src + (size_t)b*K*NCLS + kk;
    float s = 0.f;
    for (int c = lane; c < K; c += 32)
        s += wr[c] * sr[(size_t)c*NCLS];
    #pragma unroll
    for (int d = 16; d > 0; d >>= 1) s += __shfl_xor_sync(0xffffffffu, s, d);
    if (lane == 0) out[(size_t)b*SMELEM + r] = s;
}

// per-batch GN + relu on a 2688-element buffer
__global__ __launch_bounds__(256) void k_sm_gn(
    const float* __restrict__ in, const float* __restrict__ gam,
    const float* __restrict__ bet, float* __restrict__ out)
{
    int b = blockIdx.x, tid = threadIdx.x;
    __shared__ float red[256];
    __shared__ float red2[256];
    __shared__ float2 mv;
    const float* src = in + (size_t)b*SMELEM;
    float s = 0.f, q = 0.f;
    for (int e = tid; e < SMELEM; e += 256) { float v = src[e]; s += v; q += v*v; }
    red[tid] = s; red2[tid] = q; __syncthreads();
    for (int st = 128; st > 0; st >>= 1) {
        if (tid < st) { red[tid] += red[tid+st]; red2[tid] += red2[tid+st]; }
        __syncthreads();
    }
    if (tid == 0) {
        float m = red[0] / (float)SMELEM;
        float var = red2[0] / (float)SMELEM - m*m;
        mv = make_float2(m, rsqrtf(var + EPS_GN));
    }
    __syncthreads();
    float m = mv.x, rs = mv.y;
    float* dst = out + (size_t)b*SMELEM;
    for (int e = tid; e < SMELEM; e += 256) {
        int o = e / NCLS;
        dst[e] = fmaxf((src[e] - m)*rs*gam[o] + bet[o], 0.f);
    }
}

// ----------------------------- tensor-core conv GEMM (tf32 mma) ------------
__global__ __launch_bounds__(256) void k_conv_tc(
    const float* __restrict__ W, const float* __restrict__ Xa,
    int stats_stage, const float* __restrict__ ga, const float* __restrict__ ba,
    int Ka, const float* __restrict__ Xb,
    float* __restrict__ Y, int K, int O)
{
    extern __shared__ float smf[];
    uint2* PA = (uint2*)smf;           // stage s: PA + s*1056  (8*132)
    float* PB = smf + 4224;            // stage s: PB + s*4224  (16*264)

    int tid = threadIdx.x;
    int lane = tid & 31, wid = tid >> 5;
    int wr = wid >> 2, wc = wid & 3;
    int b = blockIdx.z;
    int n0 = blockIdx.x * 256, o0 = blockIdx.y * 128;

    float mean = 0.f, rstd = 0.f;
    if (stats_stage >= 0) { float2 st = g_stats[stats_stage*NB + b]; mean = st.x; rstd = st.y; }

    int a_o = tid >> 1;
    int a_h = tid & 1;
    int b_k = tid >> 4;
    int b_nb = (tid & 15) * 4;

    float acc[4][8][4];
    #pragma unroll
    for (int i = 0; i < 4; i++)
        #pragma unroll
        for (int j = 0; j < 8; j++)
            #pragma unroll
            for (int r = 0; r < 4; r++) acc[i][j][r] = 0.f;

    float4 ra0, ra1, rb[4];
    float gk = 1.f, bk = 0.f;
    bool dogn = false;

    auto LOAD = [&](int k0) {
        const float* wr_ = &W[(size_t)(o0 + a_o)*K + k0 + a_h*8];
        ra0 = *(const float4*)wr_;
        ra1 = *(const float4*)(wr_ + 4);
        int k = k0 + b_k;
        const float* src;
        if (k < Ka) src = &Xa[((size_t)b*Ka + k)*NSP + n0];
        else        src = &Xb[((size_t)b*(K - Ka) + (k - Ka))*NSP + n0];
        #pragma unroll
        for (int q = 0; q < 4; q++) rb[q] = *(const float4*)&src[b_nb + q*64];
        dogn = (stats_stage >= 0) && (k < Ka);
        if (dogn) { gk = ga[k]; bk = ba[k]; }
    };
    auto STORE = [&](int s) {
        uint2* pa = PA + s*1056;
        int i0 = a_h * 4;
        pa[(i0+0)*132 + a_o] = make_uint2(f2tf(ra0.x), f2tf(ra1.x));
        pa[(i0+1)*132 + a_o] = make_uint2(f2tf(ra0.y), f2tf(ra1.y));
        pa[(i0+2)*132 + a_o] = make_uint2(f2tf(ra0.z), f2tf(ra1.z));
        pa[(i0+3)*132 + a_o] = make_uint2(f2tf(ra0.w), f2tf(ra1.w));
        float* pb = PB + s*4224;
        #pragma unroll
        for (int q = 0; q < 4; q++) {
            float4 v = rb[q];
            if (dogn) {
                v.x = fmaxf((v.x - mean)*rstd*gk + bk, 0.f);
                v.y = fmaxf((v.y - mean)*rstd*gk + bk, 0.f);
                v.z = fmaxf((v.z - mean)*rstd*gk + bk, 0.f);
                v.w = fmaxf((v.w - mean)*rstd*gk + bk, 0.f);
            }
            float4 t;
            t.x = __uint_as_float(f2tf(v.x));
            t.y = __uint_as_float(f2tf(v.y));
            t.z = __uint_as_float(f2tf(v.z));
            t.w = __uint_as_float(f2tf(v.w));
            *(float4*)&pb[b_k*264 + b_nb + q*64] = t;
        }
    };
    auto COMPUTE = [&](int s) {
        uint2* pa = PA + s*1056;
        float* pb = PB + s*4224;
        int row4 = lane >> 2, kq = lane & 3;
        #pragma unroll
        for (int ks = 0; ks < 2; ks++) {
            uint32_t Af[4][4];
            #pragma unroll
            for (int mt = 0; mt < 4; mt++) {
                int m = wr*64 + mt*16 + row4;
                uint2 lo = pa[(ks*4 + kq)*132 + m];
                uint2 hi = pa[(ks*4 + kq)*132 + m + 8];
                Af[mt][0] = lo.x; Af[mt][1] = hi.x; Af[mt][2] = lo.y; Af[mt][3] = hi.y;
            }
            uint32_t Bf[8][2];
            #pragma unroll
            for (int nt = 0; nt < 8; nt++) {
                int n = wc*64 + nt*8 + row4;
                Bf[nt][0] = __float_as_uint(pb[(ks*8 + kq    )*264 + n]);
                Bf[nt][1] = __float_as_uint(pb[(ks*8 + kq + 4)*264 + n]);
            }
            #pragma unroll
            for (int mt = 0; mt < 4; mt++)
                #pragma unroll
                for (int nt = 0; nt < 8; nt++) {
                    float* c = acc[mt][nt];
                    asm volatile(
                        "mma.sync.aligned.m16n8k8.row.col.f32.tf32.tf32.f32 "
                        "{%0,%1,%2,%3}, {%4,%5,%6,%7}, {%8,%9}, {%0,%1,%2,%3};"
                        : "+f"(c[0]), "+f"(c[1]), "+f"(c[2]), "+f"(c[3])
                        : "r"(Af[mt][0]), "r"(Af[mt][1]), "r"(Af[mt][2]), "r"(Af[mt][3]),
                          "r"(Bf[nt][0]), "r"(Bf[nt][1]));
                }
        }
    };

    int KT = K >> 4;
    LOAD(0);
    STORE(0);
    __syncthreads();
    for (int kt = 0; kt < KT; kt++) {
        int cur = kt & 1;
        if (kt + 1 < KT) LOAD((kt + 1) << 4);
        COMPUTE(cur);
        if (kt + 1 < KT) STORE(1 - cur);
        __syncthreads();
    }

    float sum = 0.f, sq = 0.f;
    int row4 = lane >> 2, c2 = (lane & 3)*2;
    #pragma unroll
    for (int mt = 0; mt < 4; mt++) {
        int row = o0 + wr*64 + mt*16 + row4;
        #pragma unroll
        for (int nt = 0; nt < 8; nt++) {
            float* c = acc[mt][nt];
            int col = n0 + wc*64 + nt*8 + c2;
            *(float2*)&Y[((size_t)b*O + row    )*NSP + col] = make_float2(c[0], c[1]);
            *(float2*)&Y[((size_t)b*O + row + 8)*NSP + col] = make_float2(c[2], c[3]);
            sum += c[0]+c[1]+c[2]+c[3];
            sq  += c[0]*c[0]+c[1]*c[1]+c[2]*c[2]+c[3]*c[3];
        }
    }
    float* red  = smf;
    float* red2 = smf + 256;
    red[tid] = sum; red2[tid] = sq;
    __syncthreads();
    for (int st = 128; st > 0; st >>= 1) {
        if (tid < st) { red[tid] += red[tid+st]; red2[tid] += red2[tid+st]; }
        __syncthreads();
    }
    if (tid == 0) {
        int pid = blockIdx.y * gridDim.x + blockIdx.x;
        g_part[b*256 + pid] = make_float2(red[0], red2[0]);
    }
}

// ----------------------------- GN stats finalize ---------------------------
__global__ __launch_bounds__(256) void k_stats_fin(int CN, int stage, int npart)
{
    int b = blockIdx.x, tid = threadIdx.x;
    __shared__ float red[256];
    __shared__ float red2[256];
    float2 v = (tid < npart) ? g_part[b*256 + tid] : make_float2(0.f, 0.f);
    red[tid] = v.x; red2[tid] = v.y; __syncthreads();
    for (int st = 128; st > 0; st >>= 1) {
        if (tid < st) { red[tid] += red[tid+st]; red2[tid] += red2[tid+st]; }
        __syncthreads();
    }
    if (tid == 0) {
        float m = red[0] / (float)CN;
        float var = red2[0] / (float)CN - m*m;
        g_stats[stage*NB + b] = make_float2(m, rsqrtf(var + EPS_GN));
    }
}

// ----------------------------- attention -----------------------------------
__global__ __launch_bounds__(128) void k_attn(const float* __restrict__ g2, const float* __restrict__ b2)
{
    extern __shared__ float sm[];
    float* q_s = sm;
    float* k_s = sm + KCDIM*128;
    float* v_s = k_s + KCDIM*NCLS;
    int b = blockIdx.y, n0 = blockIdx.x * 128;
    int tid = threadIdx.x;

    float2 st = g_stats[1*NB + b];
    float mean = st.x, rstd = st.y;

    for (int e = tid; e < KCDIM*128; e += 128) {
        int c = e >> 7, px = e & 127;
        float raw = g_q2[((size_t)b*KCDIM + c)*NSP + n0 + px];
        float v = (raw - mean)*rstd*g2[c] + b2[c];
        q_s[c*128 + px] = fmaxf(v, 0.f);
    }
    for (int e = tid; e < KCDIM*NCLS; e += 128) {
        // kmat/vmat layout: [b][o*21+kk] -> need k_s[c*NCLS+kk] == same layout
        k_s[e] = g_kmat[(size_t)b*SMELEM + e];
        v_s[e] = g_vmat[(size_t)b*SMELEM + e];
    }
    __syncthreads();

    int px = tid;
    float s[NCLS];
    #pragma unroll
    for (int kk = 0; kk < NCLS; kk++) s[kk] = 0.f;
    for (int c = 0; c < KCDIM; c++) {
        float qv = q_s[c*128 + px];
        #pragma unroll
        for (int kk = 0; kk < NCLS; kk++) s[kk] += qv * k_s[c*NCLS + kk];
    }
    const float scale = 0.0883883476483184f;
    float mx = -3.4e38f;
    #pragma unroll
    for (int kk = 0; kk < NCLS; kk++) { s[kk] *= scale; mx = fmaxf(mx, s[kk]); }
    float ssum = 0.f;
    #pragma unroll
    for (int kk = 0; kk < NCLS; kk++) { s[kk] = __expf(s[kk] - mx); ssum += s[kk]; }
    float inv = 1.f / ssum;
    #pragma unroll
    for (int kk = 0; kk < NCLS; kk++) s[kk] *= inv;

    for (int c = 0; c < KCDIM; c++) {
        float a = 0.f;
        #pragma unroll
        for (int kk = 0; kk < NCLS; kk++) a += s[kk] * v_s[c*NCLS + kk];
        g_att[((size_t)b*KCDIM + c)*NSP + n0 + px] = a;
    }
}

// ----------------------------- final GN + relu on d_out --------------------
__global__ __launch_bounds__(256) void k_gnfinal(float* __restrict__ Y,
                                                 const float* __restrict__ g,
                                                 const float* __restrict__ bb)
{
    size_t e = ((size_t)blockIdx.x*256 + threadIdx.x)*4;
    int b = (int)(e / ((size_t)CDIM*NSP));
    int c = (int)((e / NSP) & (CDIM-1));
    float2 st = g_stats[3*NB + b];
    float m = st.x, r = st.y;
    float gm = g[c], bt = bb[c];
    float4 v = *(float4*)&Y[e];
    v.x = fmaxf((v.x - m)*r*gm + bt, 0.f);
    v.y = fmaxf((v.y - m)*r*gm + bt, 0.f);
    v.z = fmaxf((v.z - m)*r*gm + bt, 0.f);
    v.w = fmaxf((v.w - m)*r*gm + bt, 0.f);
    *(float4*)&Y[e] = v;
}

// ----------------------------- host ----------------------------------------
extern "C" void kernel_launch(void* const* d_in, const int* in_sizes, int n_in,
                              void* d_out, int out_size)
{
    const float* feats   = (const float*)d_in[0];
    const float* out_aux = (const float*)d_in[1];
    const float* fp_w1 = (const float*)d_in[2];
    const float* fp_g1 = (const float*)d_in[3];
    const float* fp_b1 = (const float*)d_in[4];
    const float* fp_w2 = (const float*)d_in[5];
    const float* fp_g2 = (const float*)d_in[6];
    const float* fp_b2 = (const float*)d_in[7];
    const float* fo_w1 = (const float*)d_in[8];
    const float* fo_g1 = (const float*)d_in[9];
    const float* fo_b1 = (const float*)d_in[10];
    const float* fo_w2 = (const float*)d_in[11];
    const float* fo_g2 = (const float*)d_in[12];
    const float* fo_b2 = (const float*)d_in[13];
    const float* fd_w  = (const float*)d_in[14];
    const float* fd_g  = (const float*)d_in[15];
    const float* fd_b  = (const float*)d_in[16];
    const float* fu_w  = (const float*)d_in[17];
    const float* fu_g  = (const float*)d_in[18];
    const float* fu_b  = (const float*)d_in[19];
    const float* cb_w  = (const float*)d_in[20];
    const float* cb_g  = (const float*)d_in[21];
    const float* cb_b  = (const float*)d_in[22];
    float* out = (float*)d_out;

    void* p;
    cudaGetSymbolAddress(&p, g_q1);  float* q1  = (float*)p;
    cudaGetSymbolAddress(&p, g_q2);  float* q2  = (float*)p;
    cudaGetSymbolAddress(&p, g_att); float* att = (float*)p;
    cudaGetSymbolAddress(&p, g_up);  float* up  = (float*)p;
    cudaGetSymbolAddress(&p, g_ctx);  float* ctx  = (float*)p;
    cudaGetSymbolAddress(&p, g_sm1);  float* sm1  = (float*)p;
    cudaGetSymbolAddress(&p, g_sm2);  float* sm2  = (float*)p;
    cudaGetSymbolAddress(&p, g_kmat); float* kmat = (float*)p;
    cudaGetSymbolAddress(&p, g_vmat); float* vmat = (float*)p;

    const int attn_smem = (KCDIM*128 + 2*KCDIM*NCLS)*4;
    cudaFuncSetAttribute(k_attn, cudaFuncAttributeMaxDynamicSharedMemorySize, attn_smem);
    const int conv_smem = (4224 + 2*4224) * 4;   // 50688 B
    cudaFuncSetAttribute(k_conv_tc, cudaFuncAttributeMaxDynamicSharedMemorySize, conv_smem);

    // ---- fork a side stream inside capture: probs/ctx/object-branch chain
    cudaStream_t s1;
    cudaStreamCreateWithFlags(&s1, cudaStreamNonBlocking);
    cudaEvent_t evF, evJ;
    cudaEventCreateWithFlags(&evF, cudaEventDisableTiming);
    cudaEventCreateWithFlags(&evJ, cudaEventDisableTiming);
    cudaEventRecord(evF, 0);
    cudaStreamWaitEvent(s1, evF, 0);

    // side chain (stream s1): probs -> ctx -> object branch (k,v)
    k_probs<<<NB*NCLS, 256, 0, s1>>>(out_aux);
    k_ctx2<<<dim3(4, NB, CTX_SLICES), 256, 0, s1>>>(feats);
    k_ctx_red<<<(NB*CDIM*NCLS + 255)/256, 256, 0, s1>>>();
    k_sm_gemm<<<NB*SMELEM/8, 256, 0, s1>>>(fo_w1, ctx, sm1, CDIM);
    k_sm_gemm<<<NB*SMELEM/8, 256, 0, s1>>>(fd_w,  ctx, sm2, CDIM);
    k_sm_gn<<<NB, 256, 0, s1>>>(sm1, fo_g1, fo_b1, sm1);
    k_sm_gn<<<NB, 256, 0, s1>>>(sm2, fd_g,  fd_b,  vmat);
    k_sm_gemm<<<NB*SMELEM/8, 256, 0, s1>>>(fo_w2, sm1, sm2, KCDIM);
    k_sm_gn<<<NB, 256, 0, s1>>>(sm2, fo_g2, fo_b2, kmat);
    cudaEventRecord(evJ, s1);

    // main chain (default stream): f_pixel conv1 -> conv2
    k_conv_tc<<<dim3(64, 1, NB), 256, conv_smem>>>(fp_w1, feats, -1, nullptr, nullptr, 256, nullptr, q1, 256, 128);
    k_stats_fin<<<NB, 256>>>(KCDIM*NSP, 0, 64);
    k_conv_tc<<<dim3(64, 1, NB), 256, conv_smem>>>(fp_w2, q1, 0, fp_g1, fp_b1, 128, nullptr, q2, 128, 128);
    k_stats_fin<<<NB, 256>>>(KCDIM*NSP, 1, 64);

    // join: attention needs q2 stats + kmat/vmat
    cudaStreamWaitEvent(0, evJ, 0);
    k_attn<<<dim3(128, NB), 128, attn_smem>>>(fp_g2, fp_b2);
    // f_up conv
    k_conv_tc<<<dim3(64, 2, NB), 256, conv_smem>>>(fu_w, att, -1, nullptr, nullptr, 128, nullptr, up, 128, 256);
    k_stats_fin<<<NB, 256>>>(CDIM*NSP, 2, 128);
    // fuse conv
    k_conv_tc<<<dim3(64, 2, NB), 256, conv_smem>>>(cb_w, up, 2, fu_g, fu_b, 256, feats, out, 512, 256);
    k_stats_fin<<<NB, 256>>>(CDIM*NSP, 3, 128);
    // final GN + relu
    k_gnfinal<<<(NB*CDIM*NSP/4)/256, 256>>>(out, cb_g, cb_b);
}

// round 6
// speedup vs baseline: 4.9701x; 1.0736x over previous
#include <cuda_runtime.h>
#include <cstdint>

#define NB 8
#define NSP 16384
#define NCLS 21
#define CDIM 256
#define KCDIM 128
#define EPS_GN 1e-5f
#define CTX_SLICES 16
#define SMELEM (KCDIM*NCLS)   // 2688

// ----------------------------- scratch (device globals, no allocation) -----
__device__ float  g_probs[(size_t)NB*NCLS*NSP];
__device__ float  g_ctx  [NB*CDIM*NCLS];
__device__ float  g_ctxp [(size_t)CTX_SLICES*NB*CDIM*NCLS];
__device__ float  g_sm1  [NB*SMELEM];
__device__ float  g_sm2  [NB*SMELEM];
__device__ float  g_kmat [NB*SMELEM];
__device__ float  g_vmat [NB*SMELEM];
__device__ float  g_q1   [(size_t)NB*KCDIM*NSP];
__device__ float  g_q2   [(size_t)NB*KCDIM*NSP];
__device__ float  g_att  [(size_t)NB*KCDIM*NSP];
__device__ float  g_up   [(size_t)NB*CDIM*NSP];
__device__ float2 g_part [4*NB*256];     // [stage][b][pid]
__device__ float2 g_stats[NB];           // final-stage stats only

__device__ __forceinline__ uint32_t f2tf(float v) {
    uint32_t u;
    asm("cvt.rna.tf32.f32 %0, %1;" : "=r"(u) : "f"(v));
    return u;
}
__device__ __forceinline__ void tf32_split(float v, float& hi, float& lo) {
    uint32_t h = f2tf(v);
    hi = __uint_as_float(h);
    lo = __uint_as_float(f2tf(v - hi));
}

#define MMA_TF32(C, A, B0, B1)                                              \
    asm volatile("mma.sync.aligned.m16n8k8.row.col.f32.tf32.tf32.f32 "      \
        "{%0,%1,%2,%3}, {%4,%5,%6,%7}, {%8,%9}, {%0,%1,%2,%3};"             \
        : "+f"((C)[0]), "+f"((C)[1]), "+f"((C)[2]), "+f"((C)[3])            \
        : "r"((A)[0]), "r"((A)[1]), "r"((A)[2]), "r"((A)[3]),               \
          "r"(B0), "r"(B1));

// ----------------------------- probs: bilinear(align_corners) + softmax ----
__global__ __launch_bounds__(256) void k_probs(const float* __restrict__ aux)
{
    int b = blockIdx.x / NCLS, k = blockIdx.x % NCLS;
    const float* src = aux + ((size_t)b*NCLS + k)*64*64;
    float* dst = g_probs + ((size_t)b*NCLS + k)*NSP;
    int tid = threadIdx.x;
    __shared__ float s_src[4096];
    __shared__ float red[256];
    __shared__ float bc;
    const float sc = 63.f/127.f;

    for (int i = tid; i < 4096; i += 256) s_src[i] = src[i];
    __syncthreads();

    float v[64];
    float mx = -3.4e38f;
    #pragma unroll
    for (int i = 0; i < 64; i++) {
        int n = tid + i*256;
        int y = n >> 7, x = n & 127;
        float sy = y*sc, sx = x*sc;
        int y0 = (int)sy, x0 = (int)sx;
        float fy = sy - (float)y0, fx = sx - (float)x0;
        int y1 = min(y0+1, 63), x1 = min(x0+1, 63);
        float a00 = s_src[y0*64+x0], a01 = s_src[y0*64+x1];
        float a10 = s_src[y1*64+x0], a11 = s_src[y1*64+x1];
        float top = a00 + (a01-a00)*fx;
        float bot = a10 + (a11-a10)*fx;
        float t = top + (bot-top)*fy;
        v[i] = t;
        mx = fmaxf(mx, t);
    }
    red[tid] = mx; __syncthreads();
    for (int s = 128; s > 0; s >>= 1) { if (tid < s) red[tid] = fmaxf(red[tid], red[tid+s]); __syncthreads(); }
    if (tid == 0) bc = red[0];
    __syncthreads();
    mx = bc;

    float sum = 0.f;
    #pragma unroll
    for (int i = 0; i < 64; i++) { v[i] = __expf(v[i] - mx); sum += v[i]; }
    __syncthreads();
    red[tid] = sum; __syncthreads();
    for (int s = 128; s > 0; s >>= 1) { if (tid < s) red[tid] += red[tid+s]; __syncthreads(); }
    if (tid == 0) bc = 1.f / red[0];
    __syncthreads();
    float inv = bc;
    #pragma unroll
    for (int i = 0; i < 64; i++) dst[tid + i*256] = v[i] * inv;
}

// -------------- ctx partials: split-K over 16 slices -----------------------
__global__ __launch_bounds__(256) void k_ctx2(const float* __restrict__ feats)
{
    __shared__ float p_s[NCLS*128];
    __shared__ float f_s[64*129];
    int b = blockIdx.y, c0 = blockIdx.x * 64, ksl = blockIdx.z;
    int tid = threadIdx.x;
    int tx = tid & 63, ty = tid >> 6;
    float acc[6] = {0,0,0,0,0,0};

    int kbeg = ksl * (NSP / CTX_SLICES);
    int kend = kbeg + (NSP / CTX_SLICES);
    for (int k0 = kbeg; k0 < kend; k0 += 128) {
        for (int e = tid; e < NCLS*128; e += 256) {
            int m = e >> 7, kk = e & 127;
            p_s[e] = g_probs[((size_t)b*NCLS + m)*NSP + k0 + kk];
        }
        for (int e = tid; e < 64*128; e += 256) {
            int r = e >> 7, kk = e & 127;
            f_s[r*129 + kk] = feats[((size_t)b*CDIM + c0 + r)*NSP + k0 + kk];
        }
        __syncthreads();
        for (int kk = 0; kk < 128; kk++) {
            float fv = f_s[tx*129 + kk];
            #pragma unroll
            for (int i = 0; i < 6; i++) {
                int m = ty + 4*i;
                if (m < NCLS) acc[i] += p_s[m*128 + kk] * fv;
            }
        }
        __syncthreads();
    }
    #pragma unroll
    for (int i = 0; i < 6; i++) {
        int m = ty + 4*i;
        if (m < NCLS)
            g_ctxp[((size_t)ksl*NB + b)*CDIM*NCLS + (size_t)(c0 + tx)*NCLS + m] = acc[i];
    }
}

__global__ __launch_bounds__(256) void k_ctx_red()
{
    int idx = blockIdx.x*256 + threadIdx.x;
    if (idx >= NB*CDIM*NCLS) return;
    float s = 0.f;
    #pragma unroll
    for (int sl = 0; sl < CTX_SLICES; sl++)
        s += g_ctxp[(size_t)sl*NB*CDIM*NCLS + idx];
    g_ctx[idx] = s;
}

// -------------- object branch: warp-per-element GEMM -----------------------
__global__ __launch_bounds__(256) void k_sm_gemm(
    const float* __restrict__ W, const float* __restrict__ src,
    float* __restrict__ out, int K)
{
    int gw = blockIdx.x * 8 + (threadIdx.x >> 5);
    int lane = threadIdx.x & 31;
    if (gw >= NB*SMELEM) return;
    int b = gw / SMELEM;
    int r = gw - b*SMELEM;
    int o = r / NCLS, kk = r - o*NCLS;
    const float* wr = W + (size_t)o*K;
    const float* sr = src + (size_t)b*K*NCLS + kk;
    float s = 0.f;
    for (int c = lane; c < K; c += 32)
        s += wr[c] * sr[(size_t)c*NCLS];
    #pragma unroll
    for (int d = 16; d > 0; d >>= 1) s += __shfl_xor_sync(0xffffffffu, s, d);
    if (lane == 0) out[(size_t)b*SMELEM + r] = s;
}

__global__ __launch_bounds__(256) void k_sm_gn(
    const float* __restrict__ in, const float* __restrict__ gam,
    const float* __restrict__ bet, float* __restrict__ out)
{
    int b = blockIdx.x, tid = threadIdx.x;
    __shared__ float red[256];
    __shared__ float red2[256];
    __shared__ float2 mv;
    const float* src = in + (size_t)b*SMELEM;
    float s = 0.f, q = 0.f;
    for (int e = tid; e < SMELEM; e += 256) { float v = src[e]; s += v; q += v*v; }
    red[tid] = s; red2[tid] = q; __syncthreads();
    for (int st = 128; st > 0; st >>= 1) {
        if (tid < st) { red[tid] += red[tid+st]; red2[tid] += red2[tid+st]; }
        __syncthreads();
    }
    if (tid == 0) {
        float m = red[0] / (float)SMELEM;
        float var = red2[0] / (float)SMELEM - m*m;
        mv = make_float2(m, rsqrtf(var + EPS_GN));
    }
    __syncthreads();
    float m = mv.x, rs = mv.y;
    float* dst = out + (size_t)b*SMELEM;
    for (int e = tid; e < SMELEM; e += 256) {
        int o = e / NCLS;
        dst[e] = fmaxf((src[e] - m)*rs*gam[o] + bet[o], 0.f);
    }
}

// ----------------------------- tensor-core conv GEMM (tf32 mma) ------------
__global__ __launch_bounds__(256) void k_conv_tc(
    const float* __restrict__ W, const float* __restrict__ Xa,
    int stage_in, int npart_in,
    const float* __restrict__ ga, const float* __restrict__ ba,
    int Ka, const float* __restrict__ Xb,
    float* __restrict__ Y, int K, int O, int stage_out)
{
    extern __shared__ float smf[];
    uint2* PA = (uint2*)smf;
    float* PB = smf + 4224;
    __shared__ float2 s_mv;

    int tid = threadIdx.x;
    int lane = tid & 31, wid = tid >> 5;
    int wr = wid >> 2, wc = wid & 3;
    int b = blockIdx.z;
    int n0 = blockIdx.x * 256, o0 = blockIdx.y * 128;

    float mean = 0.f, rstd = 0.f;
    if (stage_in >= 0) {
        if (tid < npart_in) {
            float2 pv = g_part[(stage_in*NB + b)*256 + tid];
            smf[tid] = pv.x; smf[256 + tid] = pv.y;
        }
        __syncthreads();
        if (tid == 0) {
            float s = 0.f, q = 0.f;
            for (int i = 0; i < npart_in; i++) { s += smf[i]; q += smf[256+i]; }
            float cn = (float)Ka * (float)NSP;
            float m = s / cn;
            float var = q / cn - m*m;
            s_mv = make_float2(m, rsqrtf(var + EPS_GN));
        }
        __syncthreads();
        mean = s_mv.x; rstd = s_mv.y;
        __syncthreads();
    }

    int a_o = tid >> 1;
    int a_h = tid & 1;
    int b_k = tid >> 4;
    int b_nb = (tid & 15) * 4;

    float acc[4][8][4];
    #pragma unroll
    for (int i = 0; i < 4; i++)
        #pragma unroll
        for (int j = 0; j < 8; j++)
            #pragma unroll
            for (int r = 0; r < 4; r++) acc[i][j][r] = 0.f;

    float4 ra0, ra1, rb[4];
    float gk = 1.f, bk = 0.f;
    bool dogn = false;

    auto LOAD = [&](int k0) {
        const float* wr_ = &W[(size_t)(o0 + a_o)*K + k0 + a_h*8];
        ra0 = *(const float4*)wr_;
        ra1 = *(const float4*)(wr_ + 4);
        int k = k0 + b_k;
        const float* src;
        if (k < Ka) src = &Xa[((size_t)b*Ka + k)*NSP + n0];
        else        src = &Xb[((size_t)b*(K - Ka) + (k - Ka))*NSP + n0];
        #pragma unroll
        for (int q = 0; q < 4; q++) rb[q] = *(const float4*)&src[b_nb + q*64];
        dogn = (stage_in >= 0) && (k < Ka);
        if (dogn) { gk = ga[k]; bk = ba[k]; }
    };
    auto STORE = [&](int s) {
        uint2* pa = PA + s*1056;
        int i0 = a_h * 4;
        pa[(i0+0)*132 + a_o] = make_uint2(f2tf(ra0.x), f2tf(ra1.x));
        pa[(i0+1)*132 + a_o] = make_uint2(f2tf(ra0.y), f2tf(ra1.y));
        pa[(i0+2)*132 + a_o] = make_uint2(f2tf(ra0.z), f2tf(ra1.z));
        pa[(i0+3)*132 + a_o] = make_uint2(f2tf(ra0.w), f2tf(ra1.w));
        float* pb = PB + s*4224;
        #pragma unroll
        for (int q = 0; q < 4; q++) {
            float4 v = rb[q];
            if (dogn) {
                v.x = fmaxf((v.x - mean)*rstd*gk + bk, 0.f);
                v.y = fmaxf((v.y - mean)*rstd*gk + bk, 0.f);
                v.z = fmaxf((v.z - mean)*rstd*gk + bk, 0.f);
                v.w = fmaxf((v.w - mean)*rstd*gk + bk, 0.f);
            }
            float4 t;
            t.x = __uint_as_float(f2tf(v.x));
            t.y = __uint_as_float(f2tf(v.y));
            t.z = __uint_as_float(f2tf(v.z));
            t.w = __uint_as_float(f2tf(v.w));
            *(float4*)&pb[b_k*264 + b_nb + q*64] = t;
        }
    };
    auto COMPUTE = [&](int s) {
        uint2* pa = PA + s*1056;
        float* pb = PB + s*4224;
        int row4 = lane >> 2, kq = lane & 3;
        #pragma unroll
        for (int ks = 0; ks < 2; ks++) {
            uint32_t Af[4][4];
            #pragma unroll
            for (int mt = 0; mt < 4; mt++) {
                int m = wr*64 + mt*16 + row4;
                uint2 lo = pa[(ks*4 + kq)*132 + m];
                uint2 hi = pa[(ks*4 + kq)*132 + m + 8];
                Af[mt][0] = lo.x; Af[mt][1] = hi.x; Af[mt][2] = lo.y; Af[mt][3] = hi.y;
            }
            uint32_t Bf[8][2];
            #pragma unroll
            for (int nt = 0; nt < 8; nt++) {
                int n = wc*64 + nt*8 + row4;
                Bf[nt][0] = __float_as_uint(pb[(ks*8 + kq    )*264 + n]);
                Bf[nt][1] = __float_as_uint(pb[(ks*8 + kq + 4)*264 + n]);
            }
            #pragma unroll
            for (int mt = 0; mt < 4; mt++)
                #pragma unroll
                for (int nt = 0; nt < 8; nt++) {
                    MMA_TF32(acc[mt][nt], Af[mt], Bf[nt][0], Bf[nt][1]);
                }
        }
    };

    int KT = K >> 4;
    LOAD(0);
    STORE(0);
    __syncthreads();
    for (int kt = 0; kt < KT; kt++) {
        int cur = kt & 1;
        if (kt + 1 < KT) LOAD((kt + 1) << 4);
        COMPUTE(cur);
        if (kt + 1 < KT) STORE(1 - cur);
        __syncthreads();
    }

    float sum = 0.f, sq = 0.f;
    int row4 = lane >> 2, c2 = (lane & 3)*2;
    #pragma unroll
    for (int mt = 0; mt < 4; mt++) {
        int row = o0 + wr*64 + mt*16 + row4;
        #pragma unroll
        for (int nt = 0; nt < 8; nt++) {
            float* c = acc[mt][nt];
            int col = n0 + wc*64 + nt*8 + c2;
            *(float2*)&Y[((size_t)b*O + row    )*NSP + col] = make_float2(c[0], c[1]);
            *(float2*)&Y[((size_t)b*O + row + 8)*NSP + col] = make_float2(c[2], c[3]);
            sum += c[0]+c[1]+c[2]+c[3];
            sq  += c[0]*c[0]+c[1]*c[1]+c[2]*c[2]+c[3]*c[3];
        }
    }
    float* red  = smf;
    float* red2 = smf + 256;
    __syncthreads();
    red[tid] = sum; red2[tid] = sq;
    __syncthreads();
    for (int st = 128; st > 0; st >>= 1) {
        if (tid < st) { red[tid] += red[tid+st]; red2[tid] += red2[tid+st]; }
        __syncthreads();
    }
    if (tid == 0) {
        int pid = blockIdx.y * gridDim.x + blockIdx.x;
        g_part[(stage_out*NB + b)*256 + pid] = make_float2(red[0], red2[0]);
    }
}

// ----------------------------- stats finalize (final stage only) -----------
__global__ __launch_bounds__(256) void k_stats_fin(int stage, int npart, float cn)
{
    int b = blockIdx.x, tid = threadIdx.x;
    __shared__ float red[256];
    __shared__ float red2[256];
    float2 v = (tid < npart) ? g_part[(stage*NB + b)*256 + tid] : make_float2(0.f, 0.f);
    red[tid] = v.x; red2[tid] = v.y; __syncthreads();
    for (int st = 128; st > 0; st >>= 1) {
        if (tid < st) { red[tid] += red[tid+st]; red2[tid] += red2[tid+st]; }
        __syncthreads();
    }
    if (tid == 0) {
        float m = red[0] / cn;
        float var = red2[0] / cn - m*m;
        g_stats[b] = make_float2(m, rsqrtf(var + EPS_GN));
    }
}

// ----------------------------- tensor-core attention -----------------------
#define QP 132
__global__ __launch_bounds__(256) void k_attn_tc(
    const float* __restrict__ g2, const float* __restrict__ b2)
{
    extern __shared__ float sm[];
    float* qhi = sm;            // 64*132
    float* qlo = sm + 8448;
    float* khi = sm + 16896;    // 32*68
    float* klo = sm + 19072;    // end 21248
    float* v_s = sm;            // phase3 alias: 128*28
    float* p_s = sm + 4096;     // 24*132
    __shared__ float sred[64], sred2[64];
    __shared__ float2 s_mv;

    int b = blockIdx.y, n0 = blockIdx.x * 128;
    int tid = threadIdx.x, lane = tid & 31, w = tid >> 5;
    int r4 = lane >> 2, q4 = lane & 3;

    if (tid < 64) {
        float2 pv = g_part[(1*NB + b)*256 + tid];
        sred[tid] = pv.x; sred2[tid] = pv.y;
    }
    __syncthreads();
    if (tid == 0) {
        float s = 0.f, q = 0.f;
        for (int i = 0; i < 64; i++) { s += sred[i]; q += sred2[i]; }
        float cn = (float)KCDIM * (float)NSP;
        float m = s / cn;
        float var = q / cn - m*m;
        s_mv = make_float2(m, rsqrtf(var + EPS_GN));
    }
    __syncthreads();
    float mean = s_mv.x, rstd = s_mv.y;

    float C1[2][2][4];
    #pragma unroll
    for (int i = 0; i < 2; i++)
        #pragma unroll
        for (int j = 0; j < 2; j++)
            #pragma unroll
            for (int r = 0; r < 4; r++) C1[i][j][r] = 0.f;

    for (int h = 0; h < 2; h++) {
        if (h) __syncthreads();
        for (int i = tid; i < 2048; i += 256) {
            int cl = i >> 5, pq = i & 31;
            int c = h*64 + cl;
            float4 v = *(const float4*)&g_q2[((size_t)b*KCDIM + c)*NSP + n0 + pq*4];
            float gg = g2[c], bb = b2[c];
            float4 hi4, lo4;
            float x;
            x = fmaxf((v.x - mean)*rstd*gg + bb, 0.f); tf32_split(x, hi4.x, lo4.x);
            x = fmaxf((v.y - mean)*rstd*gg + bb, 0.f); tf32_split(x, hi4.y, lo4.y);
            x = fmaxf((v.z - mean)*rstd*gg + bb, 0.f); tf32_split(x, hi4.z, lo4.z);
            x = fmaxf((v.w - mean)*rstd*gg + bb, 0.f); tf32_split(x, hi4.w, lo4.w);
            *(float4*)&qhi[cl*QP + pq*4] = hi4;
            *(float4*)&qlo[cl*QP + pq*4] = lo4;
        }
        for (int i = tid; i < 2176; i += 256) {
            int cls = i / 68, cc = i - cls*68;
            float val = 0.f;
            if (cls < NCLS && cc < 64)
                val = g_kmat[(size_t)b*SMELEM + (size_t)(h*64 + cc)*NCLS + cls];
            float hv, lv; tf32_split(val, hv, lv);
            khi[i] = hv; klo[i] = lv;
        }
        __syncthreads();

        #pragma unroll
        for (int ks = 0; ks < 8; ks++) {
            int kb = ks*8;
            uint32_t Ah[2][4], Al[2][4];
            #pragma unroll
            for (int mt = 0; mt < 2; mt++) {
                int m = mt*16 + r4;
                Ah[mt][0] = __float_as_uint(khi[(m  )*68 + kb + q4]);
                Ah[mt][1] = __float_as_uint(khi[(m+8)*68 + kb + q4]);
                Ah[mt][2] = __float_as_uint(khi[(m  )*68 + kb + q4 + 4]);
                Ah[mt][3] = __float_as_uint(khi[(m+8)*68 + kb + q4 + 4]);
                Al[mt][0] = __float_as_uint(klo[(m  )*68 + kb + q4]);
                Al[mt][1] = __float_as_uint(klo[(m+8)*68 + kb + q4]);
                Al[mt][2] = __float_as_uint(klo[(m  )*68 + kb + q4 + 4]);
                Al[mt][3] = __float_as_uint(klo[(m+8)*68 + kb + q4 + 4]);
            }
            uint32_t Bh[2][2], Bl[2][2];
            #pragma unroll
            for (int nt = 0; nt < 2; nt++) {
                int n = w*16 + nt*8 + r4;
                Bh[nt][0] = __float_as_uint(qhi[(kb + q4    )*QP + n]);
                Bh[nt][1] = __float_as_uint(qhi[(kb + q4 + 4)*QP + n]);
                Bl[nt][0] = __float_as_uint(qlo[(kb + q4    )*QP + n]);
                Bl[nt][1] = __float_as_uint(qlo[(kb + q4 + 4)*QP + n]);
            }
            #pragma unroll
            for (int mt = 0; mt < 2; mt++)
                #pragma unroll
                for (int nt = 0; nt < 2; nt++) {
                    MMA_TF32(C1[mt][nt], Ah[mt], Bh[nt][0], Bh[nt][1]);
                    MMA_TF32(C1[mt][nt], Ah[mt], Bl[nt][0], Bl[nt][1]);
                    MMA_TF32(C1[mt][nt], Al[mt], Bh[nt][0], Bh[nt][1]);
                }
        }
    }

    const float scale = 0.0883883476483184f;
    bool v2ok = (r4 < 5);
    float P[2][2][3];
    #pragma unroll
    for (int nt = 0; nt < 2; nt++) {
        #pragma unroll
        for (int j = 0; j < 2; j++) {
            float v0 = C1[0][nt][j    ] * scale;
            float v1 = C1[0][nt][j + 2] * scale;
            float v2 = C1[1][nt][j    ] * scale;
            float mx = fmaxf(v0, v1);
            if (v2ok) mx = fmaxf(mx, v2);
            #pragma unroll
            for (int d = 4; d <= 16; d <<= 1)
                mx = fmaxf(mx, __shfl_xor_sync(0xffffffffu, mx, d));
            float e0 = __expf(v0 - mx);
            float e1 = __expf(v1 - mx);
            float e2 = v2ok ? __expf(v2 - mx) : 0.f;
            float ssum = e0 + e1 + e2;
            #pragma unroll
            for (int d = 4; d <= 16; d <<= 1)
                ssum += __shfl_xor_sync(0xffffffffu, ssum, d);
            float inv = 1.f / ssum;
            P[nt][j][0] = e0 * inv;
            P[nt][j][1] = e1 * inv;
            P[nt][j][2] = e2 * inv;
        }
    }

    __syncthreads();

    for (int i = tid; i < 24*QP; i += 256) p_s[i] = 0.f;
    for (int i = tid; i < 128*28; i += 256) {
        int kc = i / 28, cls = i - kc*28;
        float val = (cls < NCLS) ? g_vmat[(size_t)b*SMELEM + (size_t)kc*NCLS + cls] : 0.f;
        v_s[i] = __uint_as_float(f2tf(val));
    }
    __syncthreads();

    #pragma unroll
    for (int nt = 0; nt < 2; nt++) {
        #pragma unroll
        for (int j = 0; j < 2; j++) {
            int px = w*16 + nt*8 + 2*q4 + j;
            p_s[(r4    )*QP + px] = __uint_as_float(f2tf(P[nt][j][0]));
            p_s[(r4 + 8)*QP + px] = __uint_as_float(f2tf(P[nt][j][1]));
            if (v2ok) p_s[(16 + r4)*QP + px] = __uint_as_float(f2tf(P[nt][j][2]));
        }
    }
    __syncthreads();

    int wm = w*16;
    uint32_t A3[3][4];
    #pragma unroll
    for (int ks = 0; ks < 3; ks++) {
        int kb = ks*8;
        A3[ks][0] = __float_as_uint(v_s[(wm + r4    )*28 + kb + q4]);
        A3[ks][1] = __float_as_uint(v_s[(wm + r4 + 8)*28 + kb + q4]);
        A3[ks][2] = __float_as_uint(v_s[(wm + r4    )*28 + kb + q4 + 4]);
        A3[ks][3] = __float_as_uint(v_s[(wm + r4 + 8)*28 + kb + q4 + 4]);
    }
    #pragma unroll
    for (int nt = 0; nt < 16; nt++) {
        float C[4] = {0.f, 0.f, 0.f, 0.f};
        #pragma unroll
        for (int ks = 0; ks < 3; ks++) {
            int kb = ks*8;
            uint32_t B0 = __float_as_uint(p_s[(kb + q4    )*QP + nt*8 + r4]);
            uint32_t B1 = __float_as_uint(p_s[(kb + q4 + 4)*QP + nt*8 + r4]);
            MMA_TF32(C, A3[ks], B0, B1);
        }
        int px = n0 + nt*8 + 2*q4;
        *(float2*)&g_att[((size_t)b*KCDIM + wm + r4    )*NSP + px] = make_float2(C[0], C[1]);
        *(float2*)&g_att[((size_t)b*KCDIM + wm + r4 + 8)*NSP + px] = make_float2(C[2], C[3]);
    }
}

// ----------------------------- final GN + relu on d_out --------------------
__global__ __launch_bounds__(256) void k_gnfinal(float* __restrict__ Y,
                                                 const float* __restrict__ g,
                                                 const float* __restrict__ bb)
{
    size_t e = ((size_t)blockIdx.x*256 + threadIdx.x)*4;
    int b = (int)(e / ((size_t)CDIM*NSP));
    int c = (int)((e / NSP) & (CDIM-1));
    float2 st = g_stats[b];
    float m = st.x, r = st.y;
    float gm = g[c], bt = bb[c];
    float4 v = *(float4*)&Y[e];
    v.x = fmaxf((v.x - m)*r*gm + bt, 0.f);
    v.y = fmaxf((v.y - m)*r*gm + bt, 0.f);
    v.z = fmaxf((v.z - m)*r*gm + bt, 0.f);
    v.w = fmaxf((v.w - m)*r*gm + bt, 0.f);
    *(float4*)&Y[e] = v;
}

// ----------------------------- host ----------------------------------------
extern "C" void kernel_launch(void* const* d_in, const int* in_sizes, int n_in,
                              void* d_out, int out_size)
{
    const float* feats   = (const float*)d_in[0];
    const float* out_aux = (const float*)d_in[1];
    const float* fp_w1 = (const float*)d_in[2];
    const float* fp_g1 = (const float*)d_in[3];
    const float* fp_b1 = (const float*)d_in[4];
    const float* fp_w2 = (const float*)d_in[5];
    const float* fp_g2 = (const float*)d_in[6];
    const float* fp_b2 = (const float*)d_in[7];
    const float* fo_w1 = (const float*)d_in[8];
    const float* fo_g1 = (const float*)d_in[9];
    const float* fo_b1 = (const float*)d_in[10];
    const float* fo_w2 = (const float*)d_in[11];
    const float* fo_g2 = (const float*)d_in[12];
    const float* fo_b2 = (const float*)d_in[13];
    const float* fd_w  = (const float*)d_in[14];
    const float* fd_g  = (const float*)d_in[15];
    const float* fd_b  = (const float*)d_in[16];
    const float* fu_w  = (const float*)d_in[17];
    const float* fu_g  = (const float*)d_in[18];
    const float* fu_b  = (const float*)d_in[19];
    const float* cb_w  = (const float*)d_in[20];
    const float* cb_g  = (const float*)d_in[21];
    const float* cb_b  = (const float*)d_in[22];
    float* out = (float*)d_out;

    void* p;
    cudaGetSymbolAddress(&p, g_q1);   float* q1   = (float*)p;
    cudaGetSymbolAddress(&p, g_q2);   float* q2   = (float*)p;
    cudaGetSymbolAddress(&p, g_att);  float* att  = (float*)p;
    cudaGetSymbolAddress(&p, g_up);   float* up   = (float*)p;
    cudaGetSymbolAddress(&p, g_ctx);  float* ctx  = (float*)p;
    cudaGetSymbolAddress(&p, g_sm1);  float* sm1  = (float*)p;
    cudaGetSymbolAddress(&p, g_sm2);  float* sm2  = (float*)p;
    cudaGetSymbolAddress(&p, g_kmat); float* kmat = (float*)p;
    cudaGetSymbolAddress(&p, g_vmat); float* vmat = (float*)p;

    const int attn_smem = 21248 * 4;            // 84992 B
    cudaFuncSetAttribute(k_attn_tc, cudaFuncAttributeMaxDynamicSharedMemorySize, attn_smem);
    const int conv_smem = (4224 + 2*4224) * 4;  // 50688 B
    cudaFuncSetAttribute(k_conv_tc, cudaFuncAttributeMaxDynamicSharedMemorySize, conv_smem);

    cudaStream_t s1;
    cudaStreamCreateWithFlags(&s1, cudaStreamNonBlocking);
    cudaEvent_t evF, evJ;
    cudaEventCreateWithFlags(&evF, cudaEventDisableTiming);
    cudaEventCreateWithFlags(&evJ, cudaEventDisableTiming);
    cudaEventRecord(evF, 0);
    cudaStreamWaitEvent(s1, evF, 0);

    // side chain (s1): probs -> ctx -> object branch (k,v)
    k_probs<<<NB*NCLS, 256, 0, s1>>>(out_aux);
    k_ctx2<<<dim3(4, NB, CTX_SLICES), 256, 0, s1>>>(feats);
    k_ctx_red<<<(NB*CDIM*NCLS + 255)/256, 256, 0, s1>>>();
    k_sm_gemm<<<NB*SMELEM/8, 256, 0, s1>>>(fo_w1, ctx, sm1, CDIM);
    k_sm_gemm<<<NB*SMELEM/8, 256, 0, s1>>>(fd_w,  ctx, sm2, CDIM);
    k_sm_gn<<<NB, 256, 0, s1>>>(sm1, fo_g1, fo_b1, sm1);
    k_sm_gn<<<NB, 256, 0, s1>>>(sm2, fd_g,  fd_b,  vmat);
    k_sm_gemm<<<NB*SMELEM/8, 256, 0, s1>>>(fo_w2, sm1, sm2, KCDIM);
    k_sm_gn<<<NB, 256, 0, s1>>>(sm2, fo_g2, fo_b2, kmat);
    cudaEventRecord(evJ, s1);

    // main chain
    k_conv_tc<<<dim3(64, 1, NB), 256, conv_smem>>>(fp_w1, feats, -1, 0, nullptr, nullptr, 256, nullptr, q1, 256, 128, 0);
    k_conv_tc<<<dim3(64, 1, NB), 256, conv_smem>>>(fp_w2, q1, 0, 64, fp_g1, fp_b1, 128, nullptr, q2, 128, 128, 1);
    cudaStreamWaitEvent(0, evJ, 0);
    k_attn_tc<<<dim3(128, NB), 256, attn_smem>>>(fp_g2, fp_b2);
    k_conv_tc<<<dim3(64, 2, NB), 256, conv_smem>>>(fu_w, att, -1, 0, nullptr, nullptr, 128, nullptr, up, 128, 256, 2);
    k_conv_tc<<<dim3(64, 2, NB), 256, conv_smem>>>(cb_w, up, 2, 128, fu_g, fu_b, 256, feats, out, 512, 256, 3);
    k_stats_fin<<<NB, 256>>>(3, 128, (float)CDIM*(float)NSP);
    k_gnfinal<<<(NB*CDIM*NSP/4)/256, 256>>>(out, cb_g, cb_b);
}